// round 14
// baseline (speedup 1.0000x reference)
#include <cuda_runtime.h>
#include <cuda_fp16.h>
#include <math.h>
#include <stdint.h>

#define B_   512
#define T_   32
#define FIN  4096
#define L_   256
#define M_   (B_*T_)
#define KCONV (3*FIN)

#define OFF_FEAT   0
#define OFF_ASSIGN 4194304
#define OFF_SEG    4210688
#define OFF_OUT    4227072
#define OFF_AT     4228096

// -------- scratch (device globals) --------
__device__ __align__(16) __half g_xh[(size_t)M_ * FIN];
__device__ __align__(16) __half g_wt[(size_t)L_ * KCONV];
__device__ __align__(16) __half g_bw[229376];
__device__ __align__(16) __half g_fhi[(size_t)M_ * L_];
__device__ __align__(16) __half g_h0hi[(size_t)M_ * 256];
__device__ float g_part[4 * M_];
__device__ float g_Amat[M_];
__device__ float g_bag[B_ * L_];
__device__ float g_h1[(size_t)M_ * 128];
__device__ int   g_kmask[B_];

// ======================= helpers =======================
__device__ __forceinline__ uint32_t smem_u32(const void* p) {
    uint32_t a;
    asm("{ .reg .u64 t; cvta.to.shared.u64 t, %1; cvt.u32.u64 %0, t; }" : "=r"(a) : "l"(p));
    return a;
}
__device__ __forceinline__ void cp16(uint32_t dst, const void* src, uint32_t sz) {
    asm volatile("cp.async.cg.shared.global [%0], [%1], 16, %2;"
                 :: "r"(dst), "l"(src), "r"(sz) : "memory");
}
__device__ __forceinline__ void ldm4(uint32_t* r, uint32_t addr) {
    asm volatile("ldmatrix.sync.aligned.m8n8.x4.shared.b16 {%0,%1,%2,%3}, [%4];"
                 : "=r"(r[0]), "=r"(r[1]), "=r"(r[2]), "=r"(r[3]) : "r"(addr));
}
__device__ __forceinline__ void mma16816(float* c, const uint32_t* a, const uint32_t* b) {
    asm volatile("mma.sync.aligned.m16n8k16.row.col.f32.f16.f16.f32 "
                 "{%0,%1,%2,%3}, {%4,%5,%6,%7}, {%8,%9}, {%0,%1,%2,%3};"
                 : "+f"(c[0]), "+f"(c[1]), "+f"(c[2]), "+f"(c[3])
                 : "r"(a[0]), "r"(a[1]), "r"(a[2]), "r"(a[3]), "r"(b[0]), "r"(b[1]));
}
__device__ __forceinline__ float tanh_fast(float x) {
    float r;
    asm("tanh.approx.f32 %0, %1;" : "=f"(r) : "f"(x));
    return r;
}
__device__ __forceinline__ float sigmoid_fast(float x) {
    return __fdividef(1.f, 1.f + __expf(-x));
}

// ======================= convert / repack kernels =======================
__global__ void conv_x_k(const float4* __restrict__ x, __half2* __restrict__ o) {
    size_t i = (size_t)blockIdx.x * 256 + threadIdx.x;
    float4 v = x[i];
    __half2 a, b;
    a.x = __float2half(v.x); a.y = __float2half(v.y);
    b.x = __float2half(v.z); b.y = __float2half(v.w);
    o[2 * i] = a; o[2 * i + 1] = b;
}

__global__ void splitw_conv_k(const float* __restrict__ w, __half* __restrict__ o) {
    int idx = blockIdx.x * 256 + threadIdx.x;
    int n = idx / KCONV;
    int k = idx - n * KCONV;
    int tap = k >> 12, c = k & 4095;
    o[idx] = __float2half(w[(size_t)n * KCONV + c * 3 + tap]);
}

__global__ void splitw_pair_k(const float* __restrict__ wa, const float* __restrict__ wb,
                              __half* __restrict__ o) {
    int idx = blockIdx.x * 256 + threadIdx.x;
    int n = idx >> 8, k = idx & 255;
    const float* w = (n & 1) ? wb : wa;
    o[idx] = __float2half(w[(size_t)(n >> 1) * 256 + k]);
}

__global__ void splitw_gen_k(const float* __restrict__ w, int srcStride, int total,
                             __half* __restrict__ o) {
    int idx = blockIdx.x * 256 + threadIdx.x;
    if (idx >= total) return;
    int n = idx >> 8, k = idx & 255;
    o[idx] = __float2half(w[(size_t)n * srcStride + k]);
}

// ======================= conv GEMM v3: A via smem, B direct-LDG =======================
// CTA 128x256, 8 warps (2m x 4n), warp tile 64x64. B fragments loaded straight from
// gmem into registers (2 LDG.32 per frag), double-buffered one ks-step ahead.
// Removes 2/3 of cp.async issue -> MMA-pipe-bound. Accumulation order unchanged.
template<int S>
__global__ void __launch_bounds__(256) conv_gemm(
    const __half* __restrict__ A, const __half* __restrict__ Bw,
    const float* __restrict__ bias,
    float* __restrict__ Cf, __half* __restrict__ Chi)
{
    constexpr uint32_t STG = 16384u;   // A-only stage
    extern __shared__ __align__(128) char smem[];
    const int tid = threadIdx.x;
    const int m0 = blockIdx.x * 128;
    const uint32_t sb = smem_u32(smem);
    const int NCH = KCONV >> 6;        // 192

    const int lane = tid & 31, warp = tid >> 5;
    const int wm = (warp >> 2) * 64, wn = (warp & 3) * 64;
    const int rsel = lane & 15, ksel = lane >> 4;
    const int g = lane >> 2, t4 = lane & 3;

    // B base pointer for this thread's fragments: frag jn at + jn*8*KCONV
    const __half* bbase = Bw + (size_t)(wn + g) * KCONV + 2 * t4;

    float acc[4][8][4];
#pragma unroll
    for (int i = 0; i < 4; i++)
#pragma unroll
        for (int j = 0; j < 8; j++)
#pragma unroll
            for (int u = 0; u < 4; u++) acc[i][j][u] = 0.f;

    auto issue_loadA = [&](int ch) {
        const uint32_t slot = (uint32_t)(ch % S);
        const int k0 = ch << 6;
        const int tap = k0 >> 12;
        const int coff = k0 & 4095;
        const int row = tid >> 1;
        long sr = (long)m0 + row + tap - 1;
        uint32_t sz = 16;
        const int tt = (row & 31) + tap - 1;
        if (tt < 0 || tt > 31) { sz = 0; sr = m0 + row; }
        const __half* src = A + sr * FIN + coff;
        const uint32_t d = sb + slot * STG + row * 128;
        const int xm = row & 7;
        const int cbase = (tid & 1) * 4;
#pragma unroll
        for (int c2 = 0; c2 < 4; c2++) {
            const int c = cbase + c2;
            cp16(d + (uint32_t)((c ^ xm) << 4), src + c * 8, sz);
        }
        asm volatile("cp.async.commit_group;" ::: "memory");
    };

    // B fragment loader: k = absolute column
    uint32_t bh[2][8][2];
    auto loadB = [&](int k, int buf) {
#pragma unroll
        for (int jn = 0; jn < 8; jn++) {
            const __half* p = bbase + (size_t)jn * 8 * KCONV + k;
            bh[buf][jn][0] = *reinterpret_cast<const uint32_t*>(p);
            bh[buf][jn][1] = *reinterpret_cast<const uint32_t*>(p + 8);
        }
    };

#pragma unroll
    for (int i = 0; i < S - 1; i++) issue_loadA(i);
    loadB(0, 0);

    for (int ch = 0; ch < NCH; ch++) {
        if (ch + S - 2 < NCH - 1)
            asm volatile("cp.async.wait_group %0;" :: "n"(S - 2) : "memory");
        else
            asm volatile("cp.async.wait_group 0;" ::: "memory");
        __syncthreads();
        if (ch + S - 1 < NCH) issue_loadA(ch + S - 1);

        const uint32_t base = sb + (uint32_t)(ch % S) * STG;
        const int k0 = ch << 6;
#pragma unroll
        for (int ks = 0; ks < 4; ks++) {
            // prefetch next B frags (next ks, or next chunk's ks0)
            if (ks < 3)            loadB(k0 + (ks + 1) * 16, (ks + 1) & 1);
            else if (ch + 1 < NCH) loadB(k0 + 64, 0);
            // A frags via LDSM
            const int kc = ks * 2 + ksel;
            uint32_t ah[4][4];
#pragma unroll
            for (int im = 0; im < 4; im++) {
                const int row = wm + im * 16 + rsel;
                const uint32_t a = base + row * 128 + (uint32_t)(((kc ^ (row & 7))) << 4);
                ldm4(ah[im], a);
            }
#pragma unroll
            for (int im = 0; im < 4; im++)
#pragma unroll
                for (int jn = 0; jn < 8; jn++)
                    mma16816(acc[im][jn], ah[im], bh[ks & 1][jn]);
        }
    }

    // ---- epilogue: bias, write fp32 + fp16 ----
#pragma unroll
    for (int im = 0; im < 4; im++) {
#pragma unroll
        for (int jn = 0; jn < 8; jn++) {
            const int n = wn + jn * 8 + t4 * 2;
            const float bv0 = bias[n], bv1 = bias[n + 1];
#pragma unroll
            for (int h = 0; h < 2; h++) {
                const int m = m0 + wm + im * 16 + g + h * 8;
                float v0 = acc[im][jn][h * 2 + 0] + bv0;
                float v1 = acc[im][jn][h * 2 + 1] + bv1;
                const size_t off = (size_t)m * 256 + n;
                *reinterpret_cast<float2*>(Cf + off) = make_float2(v0, v1);
                __half2 ph;
                ph.x = __float2half(v0); ph.y = __float2half(v1);
                *reinterpret_cast<__half2*>(Chi + off) = ph;
            }
        }
    }
}

// ======================= small HMMA GEMM (unchanged) =======================
template<int EPI, int S>
__global__ void __launch_bounds__(256, 2) mm_gemm(
    const __half* __restrict__ Ahi, int ldA,
    const __half* __restrict__ Bw, int ldB,
    const float* __restrict__ bias, const float* __restrict__ exCol,
    const float* __restrict__ exW,
    float* __restrict__ Cf, __half* __restrict__ Chi,
    int N, int K)
{
    constexpr uint32_t STG  = 32768u;
    constexpr uint32_t BOFF = 16384u;
    extern __shared__ __align__(128) char smem[];
    const int tid = threadIdx.x;
    const int m0 = blockIdx.y * 128;
    const int n0 = blockIdx.x * 128;
    const uint32_t sb = smem_u32(smem);
    const int NCH = K >> 6;

    const int lane = tid & 31, warp = tid >> 5;
    const int wm = (warp >> 2) * 64, wn = (warp & 3) * 32;
    const int rsel = lane & 15, ksel = lane >> 4;

    float acc[4][4][4];
#pragma unroll
    for (int i = 0; i < 4; i++)
#pragma unroll
        for (int j = 0; j < 4; j++)
#pragma unroll
            for (int u = 0; u < 4; u++) acc[i][j][u] = 0.f;

    auto issue_load = [&](int ch) {
        const uint32_t slot = (uint32_t)(ch % S);
        const int k0 = ch << 6;
        if (tid < 128) {
            const __half* src = Ahi + (size_t)(m0 + tid) * ldA + k0;
            const uint32_t d = sb + slot * STG + tid * 128;
            const int xm = tid & 7;
#pragma unroll
            for (int c = 0; c < 8; c++)
                cp16(d + (uint32_t)((c ^ xm) << 4), src + c * 8, 16);
        } else {
            const int row = tid - 128;
            const __half* src = Bw + (size_t)(n0 + row) * ldB + k0;
            const uint32_t d = sb + slot * STG + BOFF + row * 128;
            const int xm = row & 7;
#pragma unroll
            for (int c = 0; c < 8; c++)
                cp16(d + (uint32_t)((c ^ xm) << 4), src + c * 8, 16);
        }
        asm volatile("cp.async.commit_group;" ::: "memory");
    };

#pragma unroll
    for (int i = 0; i < S - 1; i++) issue_load(i);

    for (int ch = 0; ch < NCH; ch++) {
        if (ch + S - 2 < NCH - 1)
            asm volatile("cp.async.wait_group %0;" :: "n"(S - 2) : "memory");
        else
            asm volatile("cp.async.wait_group 0;" ::: "memory");
        __syncthreads();
        if (ch + S - 1 < NCH) issue_load(ch + S - 1);

        const uint32_t base = sb + (uint32_t)(ch % S) * STG;
#pragma unroll
        for (int ks = 0; ks < 4; ks++) {
            const int kc = ks * 2 + ksel;
            uint32_t ah[4][4];
#pragma unroll
            for (int im = 0; im < 4; im++) {
                const int row = wm + im * 16 + rsel;
                const uint32_t a = base + row * 128 + (uint32_t)(((kc ^ (row & 7))) << 4);
                ldm4(ah[im], a);
            }
            uint32_t bh[4][2];
#pragma unroll
            for (int j2 = 0; j2 < 2; j2++) {
                const int row = wn + j2 * 16 + rsel;
                const uint32_t a = base + BOFF + row * 128 + (uint32_t)(((kc ^ (row & 7))) << 4);
                uint32_t t[4];
                ldm4(t, a);
                bh[j2 * 2][0] = t[0]; bh[j2 * 2][1] = t[2];
                bh[j2 * 2 + 1][0] = t[1]; bh[j2 * 2 + 1][1] = t[3];
            }
#pragma unroll
            for (int im = 0; im < 4; im++)
#pragma unroll
                for (int jn = 0; jn < 4; jn++)
                    mma16816(acc[im][jn], ah[im], bh[jn]);
        }
    }

    const int g = lane >> 2, t4 = lane & 3;

    if (EPI == 5) {
        float part[4][2];
#pragma unroll
        for (int im = 0; im < 4; im++)
#pragma unroll
            for (int h = 0; h < 2; h++) {
                float p = 0.f;
#pragma unroll
                for (int jn = 0; jn < 4; jn++) {
                    const int n = n0 + wn + jn * 8 + t4 * 2;
                    const int d = n >> 1;
                    float v = acc[im][jn][h * 2 + 0] + bias[d];
                    float u = acc[im][jn][h * 2 + 1] + exCol[d];
                    p += tanh_fast(v) * sigmoid_fast(u) * exW[d];
                }
                p += __shfl_xor_sync(0xffffffffu, p, 1);
                p += __shfl_xor_sync(0xffffffffu, p, 2);
                part[im][h] = p;
            }
        __syncthreads();
        float* sred = reinterpret_cast<float*>(smem);
        if (t4 == 0) {
#pragma unroll
            for (int im = 0; im < 4; im++)
#pragma unroll
                for (int h = 0; h < 2; h++) {
                    const int lm = wm + im * 16 + g + h * 8;
                    sred[(warp & 3) * 128 + lm] = part[im][h];
                }
        }
        __syncthreads();
        if (tid < 128) {
            float s = sred[tid] + sred[128 + tid] + sred[256 + tid] + sred[384 + tid];
            Cf[(size_t)blockIdx.x * M_ + m0 + tid] = s;
        }
        return;
    }

#pragma unroll
    for (int im = 0; im < 4; im++) {
#pragma unroll
        for (int jn = 0; jn < 4; jn++) {
            const int n = n0 + wn + jn * 8 + t4 * 2;
            const float bv0 = bias[n], bv1 = bias[n + 1];
            float ew0 = 0.f, ew1 = 0.f;
            if (EPI == 2) { ew0 = exW[(size_t)n * 257]; ew1 = exW[(size_t)(n + 1) * 257]; }
#pragma unroll
            for (int h = 0; h < 2; h++) {
                const int m = m0 + wm + im * 16 + g + h * 8;
                float v0 = acc[im][jn][h * 2 + 0] + bv0;
                float v1 = acc[im][jn][h * 2 + 1] + bv1;
                if (EPI == 2) {
                    const float ec = exCol[m];
                    v0 += ec * ew0; v1 += ec * ew1;
                }
                if (EPI == 2 || EPI == 3) { v0 = fmaxf(v0, 0.f); v1 = fmaxf(v1, 0.f); }
                const size_t off = (size_t)m * N + n;
                if (EPI != 2)
                    *reinterpret_cast<float2*>(Cf + off) = make_float2(v0, v1);
                if (EPI == 2) {
                    __half2 ph;
                    ph.x = __float2half(v0); ph.y = __float2half(v1);
                    *reinterpret_cast<__half2*>(Chi + off) = ph;
                }
            }
        }
    }
}

// ======================= gated final combine =======================
__global__ void __launch_bounds__(256) gatedfin_k(
    const float* __restrict__ part, const float* __restrict__ gb,
    float* __restrict__ Amat)
{
    int m = blockIdx.x * 256 + threadIdx.x;
    Amat[m] = part[m] + part[M_ + m] + part[2 * M_ + m] + part[3 * M_ + m] + gb[0];
}

// ======================= softmax over T + bag + At =======================
__global__ void __launch_bounds__(256) softbag_kernel(
    const float* __restrict__ Amat, const float* __restrict__ feat,
    float* __restrict__ bag, float* __restrict__ outAt)
{
    __shared__ float p[32];
    int b = blockIdx.x;
    int tid = threadIdx.x;
    if (tid < 32) {
        float v = Amat[b * 32 + tid];
        outAt[b * 32 + tid] = v;
        float mx = v;
#pragma unroll
        for (int o = 16; o; o >>= 1) mx = fmaxf(mx, __shfl_xor_sync(0xffffffffu, mx, o));
        float e = expf(v - mx);
        float s = e;
#pragma unroll
        for (int o = 16; o; o >>= 1) s += __shfl_xor_sync(0xffffffffu, s, o);
        p[tid] = e / s;
    }
    __syncthreads();
    float acc = 0.f;
#pragma unroll 8
    for (int t = 0; t < 32; t++) acc += p[t] * feat[(size_t)(b * 32 + t) * 256 + tid];
    bag[b * 256 + tid] = acc;
}

// ======================= bag classifier =======================
__global__ void __launch_bounds__(256) bagclf_kernel(
    const float* __restrict__ bag,
    const float* __restrict__ w0, const float* __restrict__ b0,
    const float* __restrict__ w1, const float* __restrict__ b1,
    const float* __restrict__ w2, const float* __restrict__ b2,
    const float* __restrict__ w3, const float* __restrict__ b3,
    float* __restrict__ outp)
{
    __shared__ float sb[8 * 256];
    __shared__ float sh[8 * 256];
    int base = blockIdx.x * 8;
    int tid = threadIdx.x;
#pragma unroll
    for (int i = 0; i < 8; i++) sb[tid + i * 256] = bag[(size_t)base * 256 + tid + i * 256];
    __syncthreads();
    {
        float acc[8] = {0, 0, 0, 0, 0, 0, 0, 0};
        const float* w = w0 + (size_t)tid * 256;
        for (int l = 0; l < 256; l++) {
            float wv = w[l];
#pragma unroll
            for (int r = 0; r < 8; r++) acc[r] += wv * sb[r * 256 + l];
        }
        float bb = b0[tid];
#pragma unroll
        for (int r = 0; r < 8; r++) sh[r * 256 + tid] = fmaxf(acc[r] + bb, 0.f);
    }
    __syncthreads();
    if (tid < 128) {
        float acc[8] = {0, 0, 0, 0, 0, 0, 0, 0};
        const float* w = w1 + (size_t)tid * 256;
        for (int l = 0; l < 256; l++) {
            float wv = w[l];
#pragma unroll
            for (int r = 0; r < 8; r++) acc[r] += wv * sh[r * 256 + l];
        }
        float bb = b1[tid];
#pragma unroll
        for (int r = 0; r < 8; r++) sb[r * 128 + tid] = fmaxf(acc[r] + bb, 0.f);
    }
    __syncthreads();
    if (tid < 32) {
        float acc[8] = {0, 0, 0, 0, 0, 0, 0, 0};
        const float* w = w2 + (size_t)tid * 128;
        for (int l = 0; l < 128; l++) {
            float wv = w[l];
#pragma unroll
            for (int r = 0; r < 8; r++) acc[r] += wv * sb[r * 128 + l];
        }
        float bb = b2[tid];
#pragma unroll
        for (int r = 0; r < 8; r++) sh[r * 32 + tid] = fmaxf(acc[r] + bb, 0.f);
    }
    __syncthreads();
    if (tid < 8) {
        float a = 0.f;
        for (int j = 0; j < 32; j++) a += w3[j] * sh[tid * 32 + j];
        float o1 = 1.f / (1.f + expf(-(a + b3[0])));
        outp[(size_t)(base + tid) * 2 + 0] = 0.5f * o1;
    }
}

// ======================= seg tail =======================
__global__ void __launch_bounds__(256) segtail_kernel(
    const float* __restrict__ h1,
    const float* __restrict__ w2, const float* __restrict__ b2,
    const float* __restrict__ w3, const float* __restrict__ b3,
    float* __restrict__ out_seg)
{
    __shared__ float sw2[128 * 32];
    __shared__ float sh1[8 * 128];
    int m0 = blockIdx.x * 8;
    int tid = threadIdx.x;
#pragma unroll
    for (int i = 0; i < 16; i++) {
        int idx = tid + i * 256;
        sw2[(idx & 127) * 32 + (idx >> 7)] = w2[idx];
    }
#pragma unroll
    for (int i = 0; i < 4; i++) {
        int idx = tid + i * 256;
        sh1[idx] = h1[(size_t)m0 * 128 + idx];
    }
    __syncthreads();
    int r = tid >> 5, j = tid & 31;
    float acc = b2[j];
#pragma unroll 8
    for (int l = 0; l < 128; l++) acc += sw2[l * 32 + j] * sh1[r * 128 + l];
    float h2 = fmaxf(acc, 0.f);
    float v = h2 * w3[j];
#pragma unroll
    for (int o = 16; o; o >>= 1) v += __shfl_xor_sync(0xffffffffu, v, o);
    if (j == 0) out_seg[m0 + r] = 1.f / (1.f + expf(-(v + b3[0])));
}

// ======================= per-sample 2-means (unchanged) =======================
__global__ void __launch_bounds__(512, 4) kmeans_assign_k(
    const float* __restrict__ feat,
    float* __restrict__ out_assign, int* __restrict__ out_mask)
{
    __shared__ float sf[32 * 256];
    __shared__ float sc[2 * 256];
    __shared__ int sassign[32];
    int b = blockIdx.x;
    int tid = threadIdx.x;
    int lane = tid & 31, w = tid >> 5;

    {
        const float4* src = reinterpret_cast<const float4*>(feat + (size_t)b * 8192);
        float4* dst = reinterpret_cast<float4*>(sf);
#pragma unroll
        for (int i = 0; i < 4; i++) dst[tid + i * 512] = src[tid + i * 512];
    }
    __syncthreads();
    if (tid < 256) {
        sc[tid] = sf[tid];
        sc[256 + tid] = sf[4096 + tid];
    }
    __syncthreads();

    unsigned prev1 = 0, prev2 = 0, final_mask = 0;
    bool done = false;
    for (int it = 0; it < 100 && !done; it++) {
        float n0 = 0.f, n1 = 0.f, d0a = 0.f, d1a = 0.f, d0b = 0.f, d1b = 0.f;
#pragma unroll
        for (int i = 0; i < 8; i++) {
            int k = lane + i * 32;
            float c0 = sc[k], c1 = sc[256 + k];
            float fa = sf[w * 256 + k], fb = sf[(w + 16) * 256 + k];
            n0 += c0 * c0; n1 += c1 * c1;
            d0a += fa * c0; d1a += fa * c1;
            d0b += fb * c0; d1b += fb * c1;
        }
#pragma unroll
        for (int o = 16; o; o >>= 1) {
            n0  += __shfl_xor_sync(0xffffffffu, n0, o);
            n1  += __shfl_xor_sync(0xffffffffu, n1, o);
            d0a += __shfl_xor_sync(0xffffffffu, d0a, o);
            d1a += __shfl_xor_sync(0xffffffffu, d1a, o);
            d0b += __shfl_xor_sync(0xffffffffu, d0b, o);
            d1b += __shfl_xor_sync(0xffffffffu, d1b, o);
        }
        if (lane == 0) {
            float inv0 = 1.f / (sqrtf(n0) + 1e-8f);
            float inv1 = 1.f / (sqrtf(n1) + 1e-8f);
            sassign[w]      = (d1a * inv1 > d0a * inv0) ? 1 : 0;
            sassign[w + 16] = (d1b * inv1 > d0b * inv0) ? 1 : 0;
        }
        __syncthreads();
        unsigned mask = __ballot_sync(0xffffffffu, sassign[lane] != 0);
        if (it >= 1 && mask == prev1) { final_mask = mask; done = true; }
        else if (it >= 2 && mask == prev2) {
            final_mask = (((99 - it) & 1) == 0) ? mask : prev1;
            done = true;
        } else {
            prev2 = prev1; prev1 = mask; final_mask = mask;
            if (it == 99) done = true;
            else if (tid < 256) {
                int cnt1 = __popc(mask), cnt0 = 32 - cnt1;
                float a0 = 0.f, a1 = 0.f;
#pragma unroll
                for (int t = 0; t < 32; t++) {
                    float fv = sf[t * 256 + tid];
                    if ((mask >> t) & 1) a1 += fv; else a0 += fv;
                }
                if (cnt0 > 0) sc[tid] = a0 / (float)cnt0;
                if (cnt1 > 0) sc[256 + tid] = a1 / (float)cnt1;
            }
        }
        __syncthreads();
    }

    if (tid < 32) {
        out_assign[b * 32 + tid] = (float)((final_mask >> tid) & 1);
        if (tid == 0) out_mask[b] = (int)final_mask;
    }
}

// ======================= output2 join =======================
__global__ void __launch_bounds__(256) out2_k(
    const int* __restrict__ mask_arr, const float* __restrict__ seg,
    float* __restrict__ outp)
{
    int b = blockIdx.x * 8 + (threadIdx.x >> 5);
    int lane = threadIdx.x & 31;
    unsigned mask = (unsigned)mask_arr[b];
    float s = seg[b * 32 + lane];
    int bit = (mask >> lane) & 1;
    float v0 = bit ? 0.f : s;
    float v1 = bit ? s : 0.f;
#pragma unroll
    for (int o = 16; o; o >>= 1) {
        v0 += __shfl_xor_sync(0xffffffffu, v0, o);
        v1 += __shfl_xor_sync(0xffffffffu, v1, o);
    }
    if (lane == 0) {
        int cnt1 = __popc(mask);
        int cnt0 = 32 - cnt1;
        float m0 = (cnt0 > 0) ? v0 / (float)cnt0 : -INFINITY;
        float m1 = (cnt1 > 0) ? v1 / (float)cnt1 : -INFINITY;
        outp[(size_t)b * 2 + 1] = 0.5f * fmaxf(m0, m1);
    }
}

// ======================= launch =======================
extern "C" void kernel_launch(void* const* d_in, const int* in_sizes, int n_in,
                              void* d_out, int out_size)
{
    const float* x      = (const float*)d_in[0];
    const float* tsn_w  = (const float*)d_in[1];
    const float* tsn_b  = (const float*)d_in[2];
    const float* aV_w   = (const float*)d_in[3];
    const float* aV_b   = (const float*)d_in[4];
    const float* aU_w   = (const float*)d_in[5];
    const float* aU_b   = (const float*)d_in[6];
    const float* gate_w = (const float*)d_in[7];
    const float* gate_b = (const float*)d_in[8];
    const float* cb_w0 = (const float*)d_in[9],  *cb_b0 = (const float*)d_in[10];
    const float* cb_w1 = (const float*)d_in[11], *cb_b1 = (const float*)d_in[12];
    const float* cb_w2 = (const float*)d_in[13], *cb_b2 = (const float*)d_in[14];
    const float* cb_w3 = (const float*)d_in[15], *cb_b3 = (const float*)d_in[16];
    const float* cs_w0 = (const float*)d_in[17], *cs_b0 = (const float*)d_in[18];
    const float* cs_w1 = (const float*)d_in[19], *cs_b1 = (const float*)d_in[20];
    const float* cs_w2 = (const float*)d_in[21], *cs_b2 = (const float*)d_in[22];
    const float* cs_w3 = (const float*)d_in[23], *cs_b3 = (const float*)d_in[24];

    float* out = (float*)d_out;
    float* feat    = out + OFF_FEAT;
    float* oAssign = out + OFF_ASSIGN;
    float* oSeg    = out + OFF_SEG;
    float* oOut    = out + OFF_OUT;
    float* oAt     = out + OFF_AT;

    __half *xh, *wt, *bw, *fhi, *h0hi;
    float *part, *Amat, *bag, *h1;
    int* kmask;
    cudaGetSymbolAddress((void**)&xh, g_xh);
    cudaGetSymbolAddress((void**)&wt, g_wt);     cudaGetSymbolAddress((void**)&bw, g_bw);
    cudaGetSymbolAddress((void**)&fhi, g_fhi);   cudaGetSymbolAddress((void**)&h0hi, g_h0hi);
    cudaGetSymbolAddress((void**)&part, g_part);
    cudaGetSymbolAddress((void**)&Amat, g_Amat); cudaGetSymbolAddress((void**)&bag, g_bag);
    cudaGetSymbolAddress((void**)&h1, g_h1);
    cudaGetSymbolAddress((void**)&kmask, g_kmask);

    static cudaStream_t s1 = nullptr, s2 = nullptr;
    static cudaEvent_t evRoot, evX1, evWt, evW, evF, evKm, evA, evSeg;
    if (s1 == nullptr) {
        cudaStreamCreateWithFlags(&s1, cudaStreamNonBlocking);
        cudaStreamCreateWithFlags(&s2, cudaStreamNonBlocking);
        cudaEventCreateWithFlags(&evRoot, cudaEventDisableTiming);
        cudaEventCreateWithFlags(&evX1,   cudaEventDisableTiming);
        cudaEventCreateWithFlags(&evWt,   cudaEventDisableTiming);
        cudaEventCreateWithFlags(&evW,    cudaEventDisableTiming);
        cudaEventCreateWithFlags(&evF,    cudaEventDisableTiming);
        cudaEventCreateWithFlags(&evKm,   cudaEventDisableTiming);
        cudaEventCreateWithFlags(&evA,    cudaEventDisableTiming);
        cudaEventCreateWithFlags(&evSeg,  cudaEventDisableTiming);
    }

    const int SMC  = 3 * 16384;   // conv: A-only, S=3 -> 48KB
    const int SMB0 = 2 * 32768;
    cudaFuncSetAttribute(conv_gemm<3>, cudaFuncAttributeMaxDynamicSharedMemorySize, SMC);
    cudaFuncSetAttribute(mm_gemm<5, 2>, cudaFuncAttributeMaxDynamicSharedMemorySize, SMB0);
    cudaFuncSetAttribute(mm_gemm<2, 2>, cudaFuncAttributeMaxDynamicSharedMemorySize, SMB0);
    cudaFuncSetAttribute(mm_gemm<3, 2>, cudaFuncAttributeMaxDynamicSharedMemorySize, SMB0);

    cudaEventRecord(evRoot, 0);
    cudaStreamWaitEvent(s1, evRoot, 0);
    cudaStreamWaitEvent(s2, evRoot, 0);

    // #1: x half0 (main); #2: x half1 (s2); #3: conv weights (s1)
    conv_x_k<<<32768, 256>>>((const float4*)x, (__half2*)xh);
    conv_x_k<<<32768, 256, 0, s2>>>((const float4*)x + 8388608, (__half2*)(xh + 33554432));
    cudaEventRecord(evX1, s2);
    splitw_conv_k<<<(L_ * KCONV) / 256, 256, 0, s1>>>(tsn_w, wt);
    cudaEventRecord(evWt, s1);

    // #4: conv GEMM v3  [PROFILED]
    cudaStreamWaitEvent(0, evWt, 0);
    cudaStreamWaitEvent(0, evX1, 0);
    conv_gemm<3><<<128, 256, SMC>>>(xh, wt, tsn_b, feat, fhi);
    cudaEventRecord(evF, 0);

    // weight repacks on s1 (overlap conv)
    splitw_pair_k<<<512, 256, 0, s1>>>(aV_w, aU_w, bw);
    splitw_gen_k<<<256, 256, 0, s1>>>(cs_w0, 257, 65536, bw + 131072);
    splitw_gen_k<<<128, 256, 0, s1>>>(cs_w1, 256, 32768, bw + 196608);
    cudaEventRecord(evW, s1);

    // kmeans on s2 after feat
    cudaStreamWaitEvent(s2, evF, 0);
    kmeans_assign_k<<<B_, 512, 0, s2>>>(feat, oAssign, kmask);
    cudaEventRecord(evKm, s2);

    // main chain: fused aVU+gated -> Amat
    cudaStreamWaitEvent(0, evW, 0);
    mm_gemm<5, 2><<<dim3(4, 128), 256, SMB0>>>(fhi, 256, bw, 256,
                                               aV_b, aU_b, gate_w,
                                               part, nullptr, 512, 256);
    gatedfin_k<<<M_ / 256, 256>>>(part, gate_b, Amat);
    cudaEventRecord(evA, 0);

    // seg chain on s1
    cudaStreamWaitEvent(s1, evA, 0);
    mm_gemm<2, 2><<<dim3(2, 128), 256, SMB0, s1>>>(fhi, 256, bw + 131072, 256,
                                                   cs_b0, Amat, cs_w0 + 256,
                                                   nullptr, h0hi, 256, 256);
    mm_gemm<3, 2><<<dim3(1, 128), 256, SMB0, s1>>>(h0hi, 256, bw + 196608, 256,
                                                   cs_b1, nullptr, nullptr,
                                                   h1, nullptr, 128, 256);
    segtail_kernel<<<M_ / 8, 256, 0, s1>>>(h1, cs_w2, cs_b2, cs_w3, cs_b3, oSeg);
    cudaEventRecord(evSeg, s1);

    // bag chain on main stream
    softbag_kernel<<<B_, 256>>>(Amat, feat, bag, oAt);
    bagclf_kernel<<<B_ / 8, 256>>>(bag, cb_w0, cb_b0, cb_w1, cb_b1,
                                   cb_w2, cb_b2, cb_w3, cb_b3, oOut);

    // join
    cudaStreamWaitEvent(0, evSeg, 0);
    cudaStreamWaitEvent(0, evKm, 0);
    out2_k<<<B_ / 8, 256>>>(kmask, oSeg, oOut);
}

// round 16
// speedup vs baseline: 1.0032x; 1.0032x over previous
#include <cuda_runtime.h>
#include <cuda_fp16.h>
#include <math.h>
#include <stdint.h>

#define B_   512
#define T_   32
#define FIN  4096
#define L_   256
#define M_   (B_*T_)
#define KCONV (3*FIN)

#define OFF_FEAT   0
#define OFF_ASSIGN 4194304
#define OFF_SEG    4210688
#define OFF_OUT    4227072
#define OFF_AT     4228096

// -------- scratch (device globals) --------
__device__ __align__(16) __half g_xh[(size_t)M_ * FIN];
__device__ __align__(16) __half g_wt[(size_t)L_ * KCONV];
__device__ __align__(16) __half g_bw[229376];
__device__ __align__(16) __half g_fhi[(size_t)M_ * L_];
__device__ __align__(16) __half g_h0hi[(size_t)M_ * 256];
__device__ __align__(16) float g_p0[(size_t)M_ * 256];   // conv split-K partials
__device__ __align__(16) float g_p1[(size_t)M_ * 256];
__device__ float g_part[4 * M_];
__device__ float g_Amat[M_];
__device__ float g_bag[B_ * L_];
__device__ float g_h1[(size_t)M_ * 128];
__device__ int   g_kmask[B_];

// ======================= helpers =======================
__device__ __forceinline__ uint32_t smem_u32(const void* p) {
    uint32_t a;
    asm("{ .reg .u64 t; cvta.to.shared.u64 t, %1; cvt.u32.u64 %0, t; }" : "=r"(a) : "l"(p));
    return a;
}
__device__ __forceinline__ void cp16(uint32_t dst, const void* src, uint32_t sz) {
    asm volatile("cp.async.cg.shared.global [%0], [%1], 16, %2;"
                 :: "r"(dst), "l"(src), "r"(sz) : "memory");
}
__device__ __forceinline__ void ldm4(uint32_t* r, uint32_t addr) {
    asm volatile("ldmatrix.sync.aligned.m8n8.x4.shared.b16 {%0,%1,%2,%3}, [%4];"
                 : "=r"(r[0]), "=r"(r[1]), "=r"(r[2]), "=r"(r[3]) : "r"(addr));
}
__device__ __forceinline__ void mma16816(float* c, const uint32_t* a, const uint32_t* b) {
    asm volatile("mma.sync.aligned.m16n8k16.row.col.f32.f16.f16.f32 "
                 "{%0,%1,%2,%3}, {%4,%5,%6,%7}, {%8,%9}, {%0,%1,%2,%3};"
                 : "+f"(c[0]), "+f"(c[1]), "+f"(c[2]), "+f"(c[3])
                 : "r"(a[0]), "r"(a[1]), "r"(a[2]), "r"(a[3]), "r"(b[0]), "r"(b[1]));
}
__device__ __forceinline__ float tanh_fast(float x) {
    float r;
    asm("tanh.approx.f32 %0, %1;" : "=f"(r) : "f"(x));
    return r;
}
__device__ __forceinline__ float sigmoid_fast(float x) {
    return __fdividef(1.f, 1.f + __expf(-x));
}

// ======================= convert / repack kernels =======================
__global__ void conv_x_k(const float4* __restrict__ x, __half2* __restrict__ o) {
    size_t i = (size_t)blockIdx.x * 256 + threadIdx.x;
    float4 v = x[i];
    __half2 a, b;
    a.x = __float2half(v.x); a.y = __float2half(v.y);
    b.x = __float2half(v.z); b.y = __float2half(v.w);
    o[2 * i] = a; o[2 * i + 1] = b;
}

__global__ void splitw_conv_k(const float* __restrict__ w, __half* __restrict__ o) {
    int idx = blockIdx.x * 256 + threadIdx.x;
    int n = idx / KCONV;
    int k = idx - n * KCONV;
    int tap = k >> 12, c = k & 4095;
    o[idx] = __float2half(w[(size_t)n * KCONV + c * 3 + tap]);
}

__global__ void splitw_pair_k(const float* __restrict__ wa, const float* __restrict__ wb,
                              __half* __restrict__ o) {
    int idx = blockIdx.x * 256 + threadIdx.x;
    int n = idx >> 8, k = idx & 255;
    const float* w = (n & 1) ? wb : wa;
    o[idx] = __float2half(w[(size_t)(n >> 1) * 256 + k]);
}

__global__ void splitw_gen_k(const float* __restrict__ w, int srcStride, int total,
                             __half* __restrict__ o) {
    int idx = blockIdx.x * 256 + threadIdx.x;
    if (idx >= total) return;
    int n = idx >> 8, k = idx & 255;
    o[idx] = __float2half(w[(size_t)n * srcStride + k]);
}

// ======================= conv GEMM (R13 body, split-K) =======================
// CTA 128x256, 8 warps (2m x 4n), warp tile 64x64, A+B via cp.async smem (48KB stage).
// Processes chunks [chunk0, chunk0+96); writes fp32 partial (no bias/fp16).
template<int S>
__global__ void __launch_bounds__(256) conv_gemm(
    const __half* __restrict__ A, const __half* __restrict__ Bw,
    float* __restrict__ Cp, int chunk0)
{
    constexpr uint32_t STG = 49152u;   // A 16KB + B 32KB
    constexpr uint32_t BOFF = 16384u;
    constexpr int NCH = 96;
    extern __shared__ __align__(128) char smem[];
    const int tid = threadIdx.x;
    const int m0 = blockIdx.x * 128;
    const uint32_t sb = smem_u32(smem);

    const int lane = tid & 31, warp = tid >> 5;
    const int wm = (warp >> 2) * 64, wn = (warp & 3) * 64;
    const int rsel = lane & 15, ksel = lane >> 4;

    float acc[4][8][4];
#pragma unroll
    for (int i = 0; i < 4; i++)
#pragma unroll
        for (int j = 0; j < 8; j++)
#pragma unroll
            for (int u = 0; u < 4; u++) acc[i][j][u] = 0.f;

    auto issue_load = [&](int ch) {
        const uint32_t slot = (uint32_t)(ch % S);
        const int k0 = (chunk0 + ch) << 6;
        if (tid < 128) {
            const int tap = k0 >> 12;
            const int coff = k0 & 4095;
            long sr = (long)m0 + tid + tap - 1;
            uint32_t sz = 16;
            const int tt = (tid & 31) + tap - 1;
            if (tt < 0 || tt > 31) { sz = 0; sr = m0 + tid; }
            const __half* src = A + sr * FIN + coff;
            const uint32_t d = sb + slot * STG + tid * 128;
            const int xm = tid & 7;
#pragma unroll
            for (int c = 0; c < 8; c++)
                cp16(d + (uint32_t)((c ^ xm) << 4), src + c * 8, sz);
        } else {
            const int r = tid - 128;
#pragma unroll
            for (int q = 0; q < 2; q++) {
                const int row = r + q * 128;
                const __half* src = Bw + (size_t)row * KCONV + k0;
                const uint32_t d = sb + slot * STG + BOFF + row * 128;
                const int xm = row & 7;
#pragma unroll
                for (int c = 0; c < 8; c++)
                    cp16(d + (uint32_t)((c ^ xm) << 4), src + c * 8, 16);
            }
        }
        asm volatile("cp.async.commit_group;" ::: "memory");
    };

#pragma unroll
    for (int i = 0; i < S - 1; i++) issue_load(i);

    for (int ch = 0; ch < NCH; ch++) {
        if (ch + S - 2 < NCH - 1)
            asm volatile("cp.async.wait_group %0;" :: "n"(S - 2) : "memory");
        else
            asm volatile("cp.async.wait_group 0;" ::: "memory");
        __syncthreads();
        if (ch + S - 1 < NCH) issue_load(ch + S - 1);

        const uint32_t base = sb + (uint32_t)(ch % S) * STG;
#pragma unroll
        for (int ks = 0; ks < 4; ks++) {
            const int kc = ks * 2 + ksel;
            uint32_t ah[4][4];
#pragma unroll
            for (int im = 0; im < 4; im++) {
                const int row = wm + im * 16 + rsel;
                const uint32_t a = base + row * 128 + (uint32_t)(((kc ^ (row & 7))) << 4);
                ldm4(ah[im], a);
            }
            uint32_t bh[8][2];
#pragma unroll
            for (int j2 = 0; j2 < 4; j2++) {
                const int row = wn + j2 * 16 + rsel;
                const uint32_t a = base + BOFF + row * 128 + (uint32_t)(((kc ^ (row & 7))) << 4);
                uint32_t t[4];
                ldm4(t, a);
                bh[j2 * 2][0] = t[0]; bh[j2 * 2][1] = t[2];
                bh[j2 * 2 + 1][0] = t[1]; bh[j2 * 2 + 1][1] = t[3];
            }
#pragma unroll
            for (int im = 0; im < 4; im++)
#pragma unroll
                for (int jn = 0; jn < 8; jn++)
                    mma16816(acc[im][jn], ah[im], bh[jn]);
        }
    }

    // ---- epilogue: raw fp32 partial ----
    const int g = lane >> 2, t4 = lane & 3;
#pragma unroll
    for (int im = 0; im < 4; im++)
#pragma unroll
        for (int jn = 0; jn < 8; jn++) {
            const int n = wn + jn * 8 + t4 * 2;
#pragma unroll
            for (int h = 0; h < 2; h++) {
                const int m = m0 + wm + im * 16 + g + h * 8;
                const size_t off = (size_t)m * 256 + n;
                *reinterpret_cast<float2*>(Cp + off) =
                    make_float2(acc[im][jn][h * 2 + 0], acc[im][jn][h * 2 + 1]);
            }
        }
}

// ======================= conv finalize: p0+p1+bias -> feat fp32 + fhi fp16 ==========
// one thread per float4; total M_*256/4 = 1,048,576 float4s -> grid 4096 x 256
__global__ void __launch_bounds__(256) conv_fin_k(
    const float4* __restrict__ p0, const float4* __restrict__ p1,
    const float* __restrict__ bias,
    float4* __restrict__ feat, __half2* __restrict__ fhi)
{
    size_t i = (size_t)blockIdx.x * 256 + threadIdx.x;
    const int nb = ((int)i & 63) * 4;
    float4 a = p0[i], b = p1[i];
    a.x += b.x + bias[nb];
    a.y += b.y + bias[nb + 1];
    a.z += b.z + bias[nb + 2];
    a.w += b.w + bias[nb + 3];
    feat[i] = a;
    __half2 h0, h1;
    h0.x = __float2half(a.x); h0.y = __float2half(a.y);
    h1.x = __float2half(a.z); h1.y = __float2half(a.w);
    fhi[2 * i] = h0; fhi[2 * i + 1] = h1;
}

// ======================= small HMMA GEMM (unchanged) =======================
template<int EPI, int S>
__global__ void __launch_bounds__(256, 2) mm_gemm(
    const __half* __restrict__ Ahi, int ldA,
    const __half* __restrict__ Bw, int ldB,
    const float* __restrict__ bias, const float* __restrict__ exCol,
    const float* __restrict__ exW,
    float* __restrict__ Cf, __half* __restrict__ Chi,
    int N, int K)
{
    constexpr uint32_t STG  = 32768u;
    constexpr uint32_t BOFF = 16384u;
    extern __shared__ __align__(128) char smem[];
    const int tid = threadIdx.x;
    const int m0 = blockIdx.y * 128;
    const int n0 = blockIdx.x * 128;
    const uint32_t sb = smem_u32(smem);
    const int NCH = K >> 6;

    const int lane = tid & 31, warp = tid >> 5;
    const int wm = (warp >> 2) * 64, wn = (warp & 3) * 32;
    const int rsel = lane & 15, ksel = lane >> 4;

    float acc[4][4][4];
#pragma unroll
    for (int i = 0; i < 4; i++)
#pragma unroll
        for (int j = 0; j < 4; j++)
#pragma unroll
            for (int u = 0; u < 4; u++) acc[i][j][u] = 0.f;

    auto issue_load = [&](int ch) {
        const uint32_t slot = (uint32_t)(ch % S);
        const int k0 = ch << 6;
        if (tid < 128) {
            const __half* src = Ahi + (size_t)(m0 + tid) * ldA + k0;
            const uint32_t d = sb + slot * STG + tid * 128;
            const int xm = tid & 7;
#pragma unroll
            for (int c = 0; c < 8; c++)
                cp16(d + (uint32_t)((c ^ xm) << 4), src + c * 8, 16);
        } else {
            const int row = tid - 128;
            const __half* src = Bw + (size_t)(n0 + row) * ldB + k0;
            const uint32_t d = sb + slot * STG + BOFF + row * 128;
            const int xm = row & 7;
#pragma unroll
            for (int c = 0; c < 8; c++)
                cp16(d + (uint32_t)((c ^ xm) << 4), src + c * 8, 16);
        }
        asm volatile("cp.async.commit_group;" ::: "memory");
    };

#pragma unroll
    for (int i = 0; i < S - 1; i++) issue_load(i);

    for (int ch = 0; ch < NCH; ch++) {
        if (ch + S - 2 < NCH - 1)
            asm volatile("cp.async.wait_group %0;" :: "n"(S - 2) : "memory");
        else
            asm volatile("cp.async.wait_group 0;" ::: "memory");
        __syncthreads();
        if (ch + S - 1 < NCH) issue_load(ch + S - 1);

        const uint32_t base = sb + (uint32_t)(ch % S) * STG;
#pragma unroll
        for (int ks = 0; ks < 4; ks++) {
            const int kc = ks * 2 + ksel;
            uint32_t ah[4][4];
#pragma unroll
            for (int im = 0; im < 4; im++) {
                const int row = wm + im * 16 + rsel;
                const uint32_t a = base + row * 128 + (uint32_t)(((kc ^ (row & 7))) << 4);
                ldm4(ah[im], a);
            }
            uint32_t bh[4][2];
#pragma unroll
            for (int j2 = 0; j2 < 2; j2++) {
                const int row = wn + j2 * 16 + rsel;
                const uint32_t a = base + BOFF + row * 128 + (uint32_t)(((kc ^ (row & 7))) << 4);
                uint32_t t[4];
                ldm4(t, a);
                bh[j2 * 2][0] = t[0]; bh[j2 * 2][1] = t[2];
                bh[j2 * 2 + 1][0] = t[1]; bh[j2 * 2 + 1][1] = t[3];
            }
#pragma unroll
            for (int im = 0; im < 4; im++)
#pragma unroll
                for (int jn = 0; jn < 4; jn++)
                    mma16816(acc[im][jn], ah[im], bh[jn]);
        }
    }

    const int g = lane >> 2, t4 = lane & 3;

    if (EPI == 5) {
        float part[4][2];
#pragma unroll
        for (int im = 0; im < 4; im++)
#pragma unroll
            for (int h = 0; h < 2; h++) {
                float p = 0.f;
#pragma unroll
                for (int jn = 0; jn < 4; jn++) {
                    const int n = n0 + wn + jn * 8 + t4 * 2;
                    const int d = n >> 1;
                    float v = acc[im][jn][h * 2 + 0] + bias[d];
                    float u = acc[im][jn][h * 2 + 1] + exCol[d];
                    p += tanh_fast(v) * sigmoid_fast(u) * exW[d];
                }
                p += __shfl_xor_sync(0xffffffffu, p, 1);
                p += __shfl_xor_sync(0xffffffffu, p, 2);
                part[im][h] = p;
            }
        __syncthreads();
        float* sred = reinterpret_cast<float*>(smem);
        if (t4 == 0) {
#pragma unroll
            for (int im = 0; im < 4; im++)
#pragma unroll
                for (int h = 0; h < 2; h++) {
                    const int lm = wm + im * 16 + g + h * 8;
                    sred[(warp & 3) * 128 + lm] = part[im][h];
                }
        }
        __syncthreads();
        if (tid < 128) {
            float s = sred[tid] + sred[128 + tid] + sred[256 + tid] + sred[384 + tid];
            Cf[(size_t)blockIdx.x * M_ + m0 + tid] = s;
        }
        return;
    }

#pragma unroll
    for (int im = 0; im < 4; im++) {
#pragma unroll
        for (int jn = 0; jn < 4; jn++) {
            const int n = n0 + wn + jn * 8 + t4 * 2;
            const float bv0 = bias[n], bv1 = bias[n + 1];
            float ew0 = 0.f, ew1 = 0.f;
            if (EPI == 2) { ew0 = exW[(size_t)n * 257]; ew1 = exW[(size_t)(n + 1) * 257]; }
#pragma unroll
            for (int h = 0; h < 2; h++) {
                const int m = m0 + wm + im * 16 + g + h * 8;
                float v0 = acc[im][jn][h * 2 + 0] + bv0;
                float v1 = acc[im][jn][h * 2 + 1] + bv1;
                if (EPI == 2) {
                    const float ec = exCol[m];
                    v0 += ec * ew0; v1 += ec * ew1;
                }
                if (EPI == 2 || EPI == 3) { v0 = fmaxf(v0, 0.f); v1 = fmaxf(v1, 0.f); }
                const size_t off = (size_t)m * N + n;
                if (EPI != 2)
                    *reinterpret_cast<float2*>(Cf + off) = make_float2(v0, v1);
                if (EPI == 2) {
                    __half2 ph;
                    ph.x = __float2half(v0); ph.y = __float2half(v1);
                    *reinterpret_cast<__half2*>(Chi + off) = ph;
                }
            }
        }
    }
}

// ======================= gated final combine =======================
__global__ void __launch_bounds__(256) gatedfin_k(
    const float* __restrict__ part, const float* __restrict__ gb,
    float* __restrict__ Amat)
{
    int m = blockIdx.x * 256 + threadIdx.x;
    Amat[m] = part[m] + part[M_ + m] + part[2 * M_ + m] + part[3 * M_ + m] + gb[0];
}

// ======================= softmax over T + bag + At =======================
__global__ void __launch_bounds__(256) softbag_kernel(
    const float* __restrict__ Amat, const float* __restrict__ feat,
    float* __restrict__ bag, float* __restrict__ outAt)
{
    __shared__ float p[32];
    int b = blockIdx.x;
    int tid = threadIdx.x;
    if (tid < 32) {
        float v = Amat[b * 32 + tid];
        outAt[b * 32 + tid] = v;
        float mx = v;
#pragma unroll
        for (int o = 16; o; o >>= 1) mx = fmaxf(mx, __shfl_xor_sync(0xffffffffu, mx, o));
        float e = expf(v - mx);
        float s = e;
#pragma unroll
        for (int o = 16; o; o >>= 1) s += __shfl_xor_sync(0xffffffffu, s, o);
        p[tid] = e / s;
    }
    __syncthreads();
    float acc = 0.f;
#pragma unroll 8
    for (int t = 0; t < 32; t++) acc += p[t] * feat[(size_t)(b * 32 + t) * 256 + tid];
    bag[b * 256 + tid] = acc;
}

// ======================= bag classifier =======================
__global__ void __launch_bounds__(256) bagclf_kernel(
    const float* __restrict__ bag,
    const float* __restrict__ w0, const float* __restrict__ b0,
    const float* __restrict__ w1, const float* __restrict__ b1,
    const float* __restrict__ w2, const float* __restrict__ b2,
    const float* __restrict__ w3, const float* __restrict__ b3,
    float* __restrict__ outp)
{
    __shared__ float sb[8 * 256];
    __shared__ float sh[8 * 256];
    int base = blockIdx.x * 8;
    int tid = threadIdx.x;
#pragma unroll
    for (int i = 0; i < 8; i++) sb[tid + i * 256] = bag[(size_t)base * 256 + tid + i * 256];
    __syncthreads();
    {
        float acc[8] = {0, 0, 0, 0, 0, 0, 0, 0};
        const float* w = w0 + (size_t)tid * 256;
        for (int l = 0; l < 256; l++) {
            float wv = w[l];
#pragma unroll
            for (int r = 0; r < 8; r++) acc[r] += wv * sb[r * 256 + l];
        }
        float bb = b0[tid];
#pragma unroll
        for (int r = 0; r < 8; r++) sh[r * 256 + tid] = fmaxf(acc[r] + bb, 0.f);
    }
    __syncthreads();
    if (tid < 128) {
        float acc[8] = {0, 0, 0, 0, 0, 0, 0, 0};
        const float* w = w1 + (size_t)tid * 256;
        for (int l = 0; l < 256; l++) {
            float wv = w[l];
#pragma unroll
            for (int r = 0; r < 8; r++) acc[r] += wv * sh[r * 256 + l];
        }
        float bb = b1[tid];
#pragma unroll
        for (int r = 0; r < 8; r++) sb[r * 128 + tid] = fmaxf(acc[r] + bb, 0.f);
    }
    __syncthreads();
    if (tid < 32) {
        float acc[8] = {0, 0, 0, 0, 0, 0, 0, 0};
        const float* w = w2 + (size_t)tid * 128;
        for (int l = 0; l < 128; l++) {
            float wv = w[l];
#pragma unroll
            for (int r = 0; r < 8; r++) acc[r] += wv * sb[r * 128 + l];
        }
        float bb = b2[tid];
#pragma unroll
        for (int r = 0; r < 8; r++) sh[r * 32 + tid] = fmaxf(acc[r] + bb, 0.f);
    }
    __syncthreads();
    if (tid < 8) {
        float a = 0.f;
        for (int j = 0; j < 32; j++) a += w3[j] * sh[tid * 32 + j];
        float o1 = 1.f / (1.f + expf(-(a + b3[0])));
        outp[(size_t)(base + tid) * 2 + 0] = 0.5f * o1;
    }
}

// ======================= seg tail =======================
__global__ void __launch_bounds__(256) segtail_kernel(
    const float* __restrict__ h1,
    const float* __restrict__ w2, const float* __restrict__ b2,
    const float* __restrict__ w3, const float* __restrict__ b3,
    float* __restrict__ out_seg)
{
    __shared__ float sw2[128 * 32];
    __shared__ float sh1[8 * 128];
    int m0 = blockIdx.x * 8;
    int tid = threadIdx.x;
#pragma unroll
    for (int i = 0; i < 16; i++) {
        int idx = tid + i * 256;
        sw2[(idx & 127) * 32 + (idx >> 7)] = w2[idx];
    }
#pragma unroll
    for (int i = 0; i < 4; i++) {
        int idx = tid + i * 256;
        sh1[idx] = h1[(size_t)m0 * 128 + idx];
    }
    __syncthreads();
    int r = tid >> 5, j = tid & 31;
    float acc = b2[j];
#pragma unroll 8
    for (int l = 0; l < 128; l++) acc += sw2[l * 32 + j] * sh1[r * 128 + l];
    float h2 = fmaxf(acc, 0.f);
    float v = h2 * w3[j];
#pragma unroll
    for (int o = 16; o; o >>= 1) v += __shfl_xor_sync(0xffffffffu, v, o);
    if (j == 0) out_seg[m0 + r] = 1.f / (1.f + expf(-(v + b3[0])));
}

// ======================= per-sample 2-means (unchanged) =======================
__global__ void __launch_bounds__(512, 4) kmeans_assign_k(
    const float* __restrict__ feat,
    float* __restrict__ out_assign, int* __restrict__ out_mask)
{
    __shared__ float sf[32 * 256];
    __shared__ float sc[2 * 256];
    __shared__ int sassign[32];
    int b = blockIdx.x;
    int tid = threadIdx.x;
    int lane = tid & 31, w = tid >> 5;

    {
        const float4* src = reinterpret_cast<const float4*>(feat + (size_t)b * 8192);
        float4* dst = reinterpret_cast<float4*>(sf);
#pragma unroll
        for (int i = 0; i < 4; i++) dst[tid + i * 512] = src[tid + i * 512];
    }
    __syncthreads();
    if (tid < 256) {
        sc[tid] = sf[tid];
        sc[256 + tid] = sf[4096 + tid];
    }
    __syncthreads();

    unsigned prev1 = 0, prev2 = 0, final_mask = 0;
    bool done = false;
    for (int it = 0; it < 100 && !done; it++) {
        float n0 = 0.f, n1 = 0.f, d0a = 0.f, d1a = 0.f, d0b = 0.f, d1b = 0.f;
#pragma unroll
        for (int i = 0; i < 8; i++) {
            int k = lane + i * 32;
            float c0 = sc[k], c1 = sc[256 + k];
            float fa = sf[w * 256 + k], fb = sf[(w + 16) * 256 + k];
            n0 += c0 * c0; n1 += c1 * c1;
            d0a += fa * c0; d1a += fa * c1;
            d0b += fb * c0; d1b += fb * c1;
        }
#pragma unroll
        for (int o = 16; o; o >>= 1) {
            n0  += __shfl_xor_sync(0xffffffffu, n0, o);
            n1  += __shfl_xor_sync(0xffffffffu, n1, o);
            d0a += __shfl_xor_sync(0xffffffffu, d0a, o);
            d1a += __shfl_xor_sync(0xffffffffu, d1a, o);
            d0b += __shfl_xor_sync(0xffffffffu, d0b, o);
            d1b += __shfl_xor_sync(0xffffffffu, d1b, o);
        }
        if (lane == 0) {
            float inv0 = 1.f / (sqrtf(n0) + 1e-8f);
            float inv1 = 1.f / (sqrtf(n1) + 1e-8f);
            sassign[w]      = (d1a * inv1 > d0a * inv0) ? 1 : 0;
            sassign[w + 16] = (d1b * inv1 > d0b * inv0) ? 1 : 0;
        }
        __syncthreads();
        unsigned mask = __ballot_sync(0xffffffffu, sassign[lane] != 0);
        if (it >= 1 && mask == prev1) { final_mask = mask; done = true; }
        else if (it >= 2 && mask == prev2) {
            final_mask = (((99 - it) & 1) == 0) ? mask : prev1;
            done = true;
        } else {
            prev2 = prev1; prev1 = mask; final_mask = mask;
            if (it == 99) done = true;
            else if (tid < 256) {
                int cnt1 = __popc(mask), cnt0 = 32 - cnt1;
                float a0 = 0.f, a1 = 0.f;
#pragma unroll
                for (int t = 0; t < 32; t++) {
                    float fv = sf[t * 256 + tid];
                    if ((mask >> t) & 1) a1 += fv; else a0 += fv;
                }
                if (cnt0 > 0) sc[tid] = a0 / (float)cnt0;
                if (cnt1 > 0) sc[256 + tid] = a1 / (float)cnt1;
            }
        }
        __syncthreads();
    }

    if (tid < 32) {
        out_assign[b * 32 + tid] = (float)((final_mask >> tid) & 1);
        if (tid == 0) out_mask[b] = (int)final_mask;
    }
}

// ======================= output2 join =======================
__global__ void __launch_bounds__(256) out2_k(
    const int* __restrict__ mask_arr, const float* __restrict__ seg,
    float* __restrict__ outp)
{
    int b = blockIdx.x * 8 + (threadIdx.x >> 5);
    int lane = threadIdx.x & 31;
    unsigned mask = (unsigned)mask_arr[b];
    float s = seg[b * 32 + lane];
    int bit = (mask >> lane) & 1;
    float v0 = bit ? 0.f : s;
    float v1 = bit ? s : 0.f;
#pragma unroll
    for (int o = 16; o; o >>= 1) {
        v0 += __shfl_xor_sync(0xffffffffu, v0, o);
        v1 += __shfl_xor_sync(0xffffffffu, v1, o);
    }
    if (lane == 0) {
        int cnt1 = __popc(mask);
        int cnt0 = 32 - cnt1;
        float m0 = (cnt0 > 0) ? v0 / (float)cnt0 : -INFINITY;
        float m1 = (cnt1 > 0) ? v1 / (float)cnt1 : -INFINITY;
        outp[(size_t)b * 2 + 1] = 0.5f * fmaxf(m0, m1);
    }
}

// ======================= launch =======================
extern "C" void kernel_launch(void* const* d_in, const int* in_sizes, int n_in,
                              void* d_out, int out_size)
{
    const float* x      = (const float*)d_in[0];
    const float* tsn_w  = (const float*)d_in[1];
    const float* tsn_b  = (const float*)d_in[2];
    const float* aV_w   = (const float*)d_in[3];
    const float* aV_b   = (const float*)d_in[4];
    const float* aU_w   = (const float*)d_in[5];
    const float* aU_b   = (const float*)d_in[6];
    const float* gate_w = (const float*)d_in[7];
    const float* gate_b = (const float*)d_in[8];
    const float* cb_w0 = (const float*)d_in[9],  *cb_b0 = (const float*)d_in[10];
    const float* cb_w1 = (const float*)d_in[11], *cb_b1 = (const float*)d_in[12];
    const float* cb_w2 = (const float*)d_in[13], *cb_b2 = (const float*)d_in[14];
    const float* cb_w3 = (const float*)d_in[15], *cb_b3 = (const float*)d_in[16];
    const float* cs_w0 = (const float*)d_in[17], *cs_b0 = (const float*)d_in[18];
    const float* cs_w1 = (const float*)d_in[19], *cs_b1 = (const float*)d_in[20];
    const float* cs_w2 = (const float*)d_in[21], *cs_b2 = (const float*)d_in[22];
    const float* cs_w3 = (const float*)d_in[23], *cs_b3 = (const float*)d_in[24];

    float* out = (float*)d_out;
    float* feat    = out + OFF_FEAT;
    float* oAssign = out + OFF_ASSIGN;
    float* oSeg    = out + OFF_SEG;
    float* oOut    = out + OFF_OUT;
    float* oAt     = out + OFF_AT;

    __half *xh, *wt, *bw, *fhi, *h0hi;
    float *p0, *p1, *part, *Amat, *bag, *h1;
    int* kmask;
    cudaGetSymbolAddress((void**)&xh, g_xh);
    cudaGetSymbolAddress((void**)&wt, g_wt);     cudaGetSymbolAddress((void**)&bw, g_bw);
    cudaGetSymbolAddress((void**)&fhi, g_fhi);   cudaGetSymbolAddress((void**)&h0hi, g_h0hi);
    cudaGetSymbolAddress((void**)&p0, g_p0);     cudaGetSymbolAddress((void**)&p1, g_p1);
    cudaGetSymbolAddress((void**)&part, g_part);
    cudaGetSymbolAddress((void**)&Amat, g_Amat); cudaGetSymbolAddress((void**)&bag, g_bag);
    cudaGetSymbolAddress((void**)&h1, g_h1);
    cudaGetSymbolAddress((void**)&kmask, g_kmask);

    static cudaStream_t s1 = nullptr, s2 = nullptr;
    static cudaEvent_t evRoot, evX0, evX1, evWt, evW, evSK1, evF, evKm, evA, evSeg;
    if (s1 == nullptr) {
        cudaStreamCreateWithFlags(&s1, cudaStreamNonBlocking);
        cudaStreamCreateWithFlags(&s2, cudaStreamNonBlocking);
        cudaEventCreateWithFlags(&evRoot, cudaEventDisableTiming);
        cudaEventCreateWithFlags(&evX0,   cudaEventDisableTiming);
        cudaEventCreateWithFlags(&evX1,   cudaEventDisableTiming);
        cudaEventCreateWithFlags(&evWt,   cudaEventDisableTiming);
        cudaEventCreateWithFlags(&evW,    cudaEventDisableTiming);
        cudaEventCreateWithFlags(&evSK1,  cudaEventDisableTiming);
        cudaEventCreateWithFlags(&evF,    cudaEventDisableTiming);
        cudaEventCreateWithFlags(&evKm,   cudaEventDisableTiming);
        cudaEventCreateWithFlags(&evA,    cudaEventDisableTiming);
        cudaEventCreateWithFlags(&evSeg,  cudaEventDisableTiming);
    }

    const int SMC  = 3 * 49152;
    const int SMB0 = 2 * 32768;
    cudaFuncSetAttribute(conv_gemm<3>, cudaFuncAttributeMaxDynamicSharedMemorySize, SMC);
    cudaFuncSetAttribute(mm_gemm<5, 2>, cudaFuncAttributeMaxDynamicSharedMemorySize, SMB0);
    cudaFuncSetAttribute(mm_gemm<2, 2>, cudaFuncAttributeMaxDynamicSharedMemorySize, SMB0);
    cudaFuncSetAttribute(mm_gemm<3, 2>, cudaFuncAttributeMaxDynamicSharedMemorySize, SMB0);

    cudaEventRecord(evRoot, 0);
    cudaStreamWaitEvent(s1, evRoot, 0);
    cudaStreamWaitEvent(s2, evRoot, 0);

    // #1: x half0 (main); #2: x half1 (s2); #3: conv weights (s1)
    conv_x_k<<<32768, 256>>>((const float4*)x, (__half2*)xh);
    cudaEventRecord(evX0, 0);
    conv_x_k<<<32768, 256, 0, s2>>>((const float4*)x + 8388608, (__half2*)(xh + 33554432));
    cudaEventRecord(evX1, s2);
    splitw_conv_k<<<(L_ * KCONV) / 256, 256, 0, s1>>>(tsn_w, wt);
    cudaEventRecord(evWt, s1);

    // #4: conv split-K half 0 (chunks 0-95), main  [PROFILED]
    cudaStreamWaitEvent(0, evWt, 0);
    cudaStreamWaitEvent(0, evX1, 0);
    conv_gemm<3><<<128, 256, SMC>>>(xh, wt, p0, 0);

    // conv split-K half 1 (chunks 96-191), s2
    cudaStreamWaitEvent(s2, evWt, 0);
    cudaStreamWaitEvent(s2, evX0, 0);
    conv_gemm<3><<<128, 256, SMC, s2>>>(xh, wt, p1, 96);
    cudaEventRecord(evSK1, s2);

    // finalize: feat fp32 + fhi fp16  (1,048,576 float4s / 256 = 4096 blocks)
    cudaStreamWaitEvent(0, evSK1, 0);
    conv_fin_k<<<4096, 256>>>((const float4*)p0, (const float4*)p1, tsn_b,
                              (float4*)feat, (__half2*)fhi);
    cudaEventRecord(evF, 0);

    // weight repacks on s1 (overlap conv)
    splitw_pair_k<<<512, 256, 0, s1>>>(aV_w, aU_w, bw);
    splitw_gen_k<<<256, 256, 0, s1>>>(cs_w0, 257, 65536, bw + 131072);
    splitw_gen_k<<<128, 256, 0, s1>>>(cs_w1, 256, 32768, bw + 196608);
    cudaEventRecord(evW, s1);

    // kmeans on s2 after feat
    cudaStreamWaitEvent(s2, evF, 0);
    kmeans_assign_k<<<B_, 512, 0, s2>>>(feat, oAssign, kmask);
    cudaEventRecord(evKm, s2);

    // main chain: fused aVU+gated -> Amat
    cudaStreamWaitEvent(0, evW, 0);
    mm_gemm<5, 2><<<dim3(4, 128), 256, SMB0>>>(fhi, 256, bw, 256,
                                               aV_b, aU_b, gate_w,
                                               part, nullptr, 512, 256);
    gatedfin_k<<<M_ / 256, 256>>>(part, gate_b, Amat);
    cudaEventRecord(evA, 0);

    // seg chain on s1
    cudaStreamWaitEvent(s1, evA, 0);
    mm_gemm<2, 2><<<dim3(2, 128), 256, SMB0, s1>>>(fhi, 256, bw + 131072, 256,
                                                   cs_b0, Amat, cs_w0 + 256,
                                                   nullptr, h0hi, 256, 256);
    mm_gemm<3, 2><<<dim3(1, 128), 256, SMB0, s1>>>(h0hi, 256, bw + 196608, 256,
                                                   cs_b1, nullptr, nullptr,
                                                   h1, nullptr, 128, 256);
    segtail_kernel<<<M_ / 8, 256, 0, s1>>>(h1, cs_w2, cs_b2, cs_w3, cs_b3, oSeg);
    cudaEventRecord(evSeg, s1);

    // bag chain on main stream
    softbag_kernel<<<B_, 256>>>(Amat, feat, bag, oAt);
    bagclf_kernel<<<B_ / 8, 256>>>(bag, cb_w0, cb_b0, cb_w1, cb_b1,
                                   cb_w2, cb_b2, cb_w3, cb_b3, oOut);

    // join
    cudaStreamWaitEvent(0, evSeg, 0);
    cudaStreamWaitEvent(0, evKm, 0);
    out2_k<<<B_ / 8, 256>>>(kmask, oSeg, oOut);
}

// round 17
// speedup vs baseline: 1.1171x; 1.1135x over previous
#include <cuda_runtime.h>
#include <cuda_fp16.h>
#include <math.h>
#include <stdint.h>

#define B_   512
#define T_   32
#define FIN  4096
#define L_   256
#define M_   (B_*T_)
#define KCONV (3*FIN)

#define OFF_FEAT   0
#define OFF_ASSIGN 4194304
#define OFF_SEG    4210688
#define OFF_OUT    4227072
#define OFF_AT     4228096

// -------- scratch (device globals) --------
__device__ __align__(16) __half g_xh[(size_t)M_ * FIN];
__device__ __align__(16) __half g_wt[(size_t)L_ * KCONV];
__device__ __align__(16) __half g_bw[229376];
__device__ __align__(16) __half g_fhi[(size_t)M_ * L_];
__device__ __align__(16) __half g_h0hi[(size_t)M_ * 256];
__device__ float g_part[4 * M_];
__device__ float g_Amat[M_];
__device__ float g_bag[B_ * L_];
__device__ float g_h1[(size_t)M_ * 128];
__device__ int   g_kmask[B_];

// ======================= helpers =======================
__device__ __forceinline__ uint32_t smem_u32(const void* p) {
    uint32_t a;
    asm("{ .reg .u64 t; cvta.to.shared.u64 t, %1; cvt.u32.u64 %0, t; }" : "=r"(a) : "l"(p));
    return a;
}
__device__ __forceinline__ void cp16(uint32_t dst, const void* src, uint32_t sz) {
    asm volatile("cp.async.cg.shared.global [%0], [%1], 16, %2;"
                 :: "r"(dst), "l"(src), "r"(sz) : "memory");
}
__device__ __forceinline__ void ldm4(uint32_t* r, uint32_t addr) {
    asm volatile("ldmatrix.sync.aligned.m8n8.x4.shared.b16 {%0,%1,%2,%3}, [%4];"
                 : "=r"(r[0]), "=r"(r[1]), "=r"(r[2]), "=r"(r[3]) : "r"(addr));
}
__device__ __forceinline__ void mma16816(float* c, const uint32_t* a, const uint32_t* b) {
    asm volatile("mma.sync.aligned.m16n8k16.row.col.f32.f16.f16.f32 "
                 "{%0,%1,%2,%3}, {%4,%5,%6,%7}, {%8,%9}, {%0,%1,%2,%3};"
                 : "+f"(c[0]), "+f"(c[1]), "+f"(c[2]), "+f"(c[3])
                 : "r"(a[0]), "r"(a[1]), "r"(a[2]), "r"(a[3]), "r"(b[0]), "r"(b[1]));
}
__device__ __forceinline__ float tanh_fast(float x) {
    float r;
    asm("tanh.approx.f32 %0, %1;" : "=f"(r) : "f"(x));
    return r;
}
__device__ __forceinline__ float sigmoid_fast(float x) {
    return __fdividef(1.f, 1.f + __expf(-x));
}

// ======================= convert / repack kernels =======================
__global__ void conv_x_k(const float4* __restrict__ x, __half2* __restrict__ o) {
    size_t i = (size_t)blockIdx.x * 256 + threadIdx.x;
    float4 v = x[i];
    __half2 a, b;
    a.x = __float2half(v.x); a.y = __float2half(v.y);
    b.x = __float2half(v.z); b.y = __float2half(v.w);
    o[2 * i] = a; o[2 * i + 1] = b;
}

__global__ void splitw_conv_k(const float* __restrict__ w, __half* __restrict__ o) {
    int idx = blockIdx.x * 256 + threadIdx.x;
    int n = idx / KCONV;
    int k = idx - n * KCONV;
    int tap = k >> 12, c = k & 4095;
    o[idx] = __float2half(w[(size_t)n * KCONV + c * 3 + tap]);
}

__global__ void splitw_pair_k(const float* __restrict__ wa, const float* __restrict__ wb,
                              __half* __restrict__ o) {
    int idx = blockIdx.x * 256 + threadIdx.x;
    int n = idx >> 8, k = idx & 255;
    const float* w = (n & 1) ? wb : wa;
    o[idx] = __float2half(w[(size_t)(n >> 1) * 256 + k]);
}

__global__ void splitw_gen_k(const float* __restrict__ w, int srcStride, int total,
                             __half* __restrict__ o) {
    int idx = blockIdx.x * 256 + threadIdx.x;
    if (idx >= total) return;
    int n = idx >> 8, k = idx & 255;
    o[idx] = __float2half(w[(size_t)n * srcStride + k]);
}

// ======================= conv GEMM v4: tap-shared A staging =======================
// CTA 128x256, 8 warps (2m x 4n), warp tile 64x64.
// Stage s = c*3 + t (64 column chunks x 3 taps). B ring 3 x 32KB (per-(c,t) weights).
// A ring 2 x (132 rows x 128B), loaded ONCE per column chunk:
//   staged row sr = 1..128  <->  x row m0 + sr - 1 (always globally valid)
//   row 130 = zeros. Tap t reads logical output row r at staged row r+t, EXCEPT
//   bag-boundary rows ((r%32)==0 & t==0, (r%32)==31 & t==2) which redirect to 130.
// Cuts A LDGSTS 3x -> total LDGSTS -22% (the binding resource).
__global__ void __launch_bounds__(256) conv_gemm(
    const __half* __restrict__ A, const __half* __restrict__ Bw,
    const float* __restrict__ bias,
    float* __restrict__ Cf, __half* __restrict__ Chi)
{
    constexpr uint32_t BSTG = 32768u;
    constexpr uint32_t AOFF = 3 * 32768u;     // 98304
    constexpr uint32_t ASTG = 16896u;         // 132 rows * 128B
    extern __shared__ __align__(128) char smem[];
    const int tid = threadIdx.x;
    const int m0 = blockIdx.x * 128;
    const uint32_t sb = smem_u32(smem);

    const int lane = tid & 31, warp = tid >> 5;
    const int wm = (warp >> 2) * 64, wn = (warp & 3) * 64;
    const int rsel = lane & 15, ksel = lane >> 4;

    // zero row (130) in both A slots
    if (tid < 32) {
        const int slot = tid >> 4;
        *reinterpret_cast<uint64_t*>(smem + AOFF + slot * ASTG + 130 * 128 + (tid & 15) * 8) = 0ull;
    }

    float acc[4][8][4];
#pragma unroll
    for (int i = 0; i < 4; i++)
#pragma unroll
        for (int j = 0; j < 8; j++)
#pragma unroll
            for (int u = 0; u < 4; u++) acc[i][j][u] = 0.f;

    auto issue_group = [&](int s) {
        const int c = s / 3;
        const int t = s - 3 * c;
        const int k0 = t * 4096 + (c << 6);
        // B: thread tid loads weight row tid, 8x16B swizzled
        {
            const __half* src = Bw + (size_t)tid * KCONV + k0;
            const uint32_t d = sb + (uint32_t)(s % 3) * BSTG + tid * 128;
            const int xm = tid & 7;
#pragma unroll
            for (int cc = 0; cc < 8; cc++)
                cp16(d + (uint32_t)((cc ^ xm) << 4), src + cc * 8, 16);
        }
        // A only on tap0 stages: staged row tid+1 = x row m0+tid (always valid)
        if (t == 0 && tid < 128) {
            const int sr = tid + 1;
            const __half* src = A + (size_t)(m0 + tid) * FIN + (c << 6);
            const uint32_t d = sb + AOFF + (uint32_t)(c & 1) * ASTG + sr * 128;
            const int xm = sr & 7;
#pragma unroll
            for (int cc = 0; cc < 8; cc++)
                cp16(d + (uint32_t)((cc ^ xm) << 4), src + cc * 8, 16);
        }
        asm volatile("cp.async.commit_group;" ::: "memory");
    };

    issue_group(0);
    issue_group(1);

    for (int s = 0; s < 192; s++) {
        if (s + 1 < 191)
            asm volatile("cp.async.wait_group 1;" ::: "memory");
        else
            asm volatile("cp.async.wait_group 0;" ::: "memory");
        __syncthreads();
        if (s + 2 < 192) issue_group(s + 2);

        const int c = s / 3;
        const int t = s - 3 * c;
        const uint32_t Bbase = sb + (uint32_t)(s % 3) * BSTG;
        const uint32_t Abase = sb + AOFF + (uint32_t)(c & 1) * ASTG;
#pragma unroll
        for (int ks = 0; ks < 4; ks++) {
            const int kc = ks * 2 + ksel;
            uint32_t ah[4][4];
#pragma unroll
            for (int im = 0; im < 4; im++) {
                const int r = wm + im * 16 + rsel;
                const bool bd = (t == 0 && (r & 31) == 0) || (t == 2 && (r & 31) == 31);
                const int srow = bd ? 130 : (r + t);
                const uint32_t a = Abase + srow * 128 + (uint32_t)(((kc ^ (srow & 7))) << 4);
                ldm4(ah[im], a);
            }
            uint32_t bh[8][2];
#pragma unroll
            for (int j2 = 0; j2 < 4; j2++) {
                const int row = wn + j2 * 16 + rsel;
                const uint32_t a = Bbase + row * 128 + (uint32_t)(((kc ^ (row & 7))) << 4);
                uint32_t tt[4];
                ldm4(tt, a);
                bh[j2 * 2][0] = tt[0]; bh[j2 * 2][1] = tt[2];
                bh[j2 * 2 + 1][0] = tt[1]; bh[j2 * 2 + 1][1] = tt[3];
            }
#pragma unroll
            for (int im = 0; im < 4; im++)
#pragma unroll
                for (int jn = 0; jn < 8; jn++)
                    mma16816(acc[im][jn], ah[im], bh[jn]);
        }
    }

    // ---- epilogue: bias, write fp32 + fp16 ----
    const int g = lane >> 2, t4 = lane & 3;
#pragma unroll
    for (int im = 0; im < 4; im++) {
#pragma unroll
        for (int jn = 0; jn < 8; jn++) {
            const int n = wn + jn * 8 + t4 * 2;
            const float bv0 = bias[n], bv1 = bias[n + 1];
#pragma unroll
            for (int h = 0; h < 2; h++) {
                const int m = m0 + wm + im * 16 + g + h * 8;
                float v0 = acc[im][jn][h * 2 + 0] + bv0;
                float v1 = acc[im][jn][h * 2 + 1] + bv1;
                const size_t off = (size_t)m * 256 + n;
                *reinterpret_cast<float2*>(Cf + off) = make_float2(v0, v1);
                __half2 ph;
                ph.x = __float2half(v0); ph.y = __float2half(v1);
                *reinterpret_cast<__half2*>(Chi + off) = ph;
            }
        }
    }
}

// ======================= small HMMA GEMM (unchanged) =======================
template<int EPI, int S>
__global__ void __launch_bounds__(256, 2) mm_gemm(
    const __half* __restrict__ Ahi, int ldA,
    const __half* __restrict__ Bw, int ldB,
    const float* __restrict__ bias, const float* __restrict__ exCol,
    const float* __restrict__ exW,
    float* __restrict__ Cf, __half* __restrict__ Chi,
    int N, int K)
{
    constexpr uint32_t STG  = 32768u;
    constexpr uint32_t BOFF = 16384u;
    extern __shared__ __align__(128) char smem[];
    const int tid = threadIdx.x;
    const int m0 = blockIdx.y * 128;
    const int n0 = blockIdx.x * 128;
    const uint32_t sb = smem_u32(smem);
    const int NCH = K >> 6;

    const int lane = tid & 31, warp = tid >> 5;
    const int wm = (warp >> 2) * 64, wn = (warp & 3) * 32;
    const int rsel = lane & 15, ksel = lane >> 4;

    float acc[4][4][4];
#pragma unroll
    for (int i = 0; i < 4; i++)
#pragma unroll
        for (int j = 0; j < 4; j++)
#pragma unroll
            for (int u = 0; u < 4; u++) acc[i][j][u] = 0.f;

    auto issue_load = [&](int ch) {
        const uint32_t slot = (uint32_t)(ch % S);
        const int k0 = ch << 6;
        if (tid < 128) {
            const __half* src = Ahi + (size_t)(m0 + tid) * ldA + k0;
            const uint32_t d = sb + slot * STG + tid * 128;
            const int xm = tid & 7;
#pragma unroll
            for (int c = 0; c < 8; c++)
                cp16(d + (uint32_t)((c ^ xm) << 4), src + c * 8, 16);
        } else {
            const int row = tid - 128;
            const __half* src = Bw + (size_t)(n0 + row) * ldB + k0;
            const uint32_t d = sb + slot * STG + BOFF + row * 128;
            const int xm = row & 7;
#pragma unroll
            for (int c = 0; c < 8; c++)
                cp16(d + (uint32_t)((c ^ xm) << 4), src + c * 8, 16);
        }
        asm volatile("cp.async.commit_group;" ::: "memory");
    };

#pragma unroll
    for (int i = 0; i < S - 1; i++) issue_load(i);

    for (int ch = 0; ch < NCH; ch++) {
        if (ch + S - 2 < NCH - 1)
            asm volatile("cp.async.wait_group %0;" :: "n"(S - 2) : "memory");
        else
            asm volatile("cp.async.wait_group 0;" ::: "memory");
        __syncthreads();
        if (ch + S - 1 < NCH) issue_load(ch + S - 1);

        const uint32_t base = sb + (uint32_t)(ch % S) * STG;
#pragma unroll
        for (int ks = 0; ks < 4; ks++) {
            const int kc = ks * 2 + ksel;
            uint32_t ah[4][4];
#pragma unroll
            for (int im = 0; im < 4; im++) {
                const int row = wm + im * 16 + rsel;
                const uint32_t a = base + row * 128 + (uint32_t)(((kc ^ (row & 7))) << 4);
                ldm4(ah[im], a);
            }
            uint32_t bh[4][2];
#pragma unroll
            for (int j2 = 0; j2 < 2; j2++) {
                const int row = wn + j2 * 16 + rsel;
                const uint32_t a = base + BOFF + row * 128 + (uint32_t)(((kc ^ (row & 7))) << 4);
                uint32_t t[4];
                ldm4(t, a);
                bh[j2 * 2][0] = t[0]; bh[j2 * 2][1] = t[2];
                bh[j2 * 2 + 1][0] = t[1]; bh[j2 * 2 + 1][1] = t[3];
            }
#pragma unroll
            for (int im = 0; im < 4; im++)
#pragma unroll
                for (int jn = 0; jn < 4; jn++)
                    mma16816(acc[im][jn], ah[im], bh[jn]);
        }
    }

    const int g = lane >> 2, t4 = lane & 3;

    if (EPI == 5) {
        float part[4][2];
#pragma unroll
        for (int im = 0; im < 4; im++)
#pragma unroll
            for (int h = 0; h < 2; h++) {
                float p = 0.f;
#pragma unroll
                for (int jn = 0; jn < 4; jn++) {
                    const int n = n0 + wn + jn * 8 + t4 * 2;
                    const int d = n >> 1;
                    float v = acc[im][jn][h * 2 + 0] + bias[d];
                    float u = acc[im][jn][h * 2 + 1] + exCol[d];
                    p += tanh_fast(v) * sigmoid_fast(u) * exW[d];
                }
                p += __shfl_xor_sync(0xffffffffu, p, 1);
                p += __shfl_xor_sync(0xffffffffu, p, 2);
                part[im][h] = p;
            }
        __syncthreads();
        float* sred = reinterpret_cast<float*>(smem);
        if (t4 == 0) {
#pragma unroll
            for (int im = 0; im < 4; im++)
#pragma unroll
                for (int h = 0; h < 2; h++) {
                    const int lm = wm + im * 16 + g + h * 8;
                    sred[(warp & 3) * 128 + lm] = part[im][h];
                }
        }
        __syncthreads();
        if (tid < 128) {
            float s = sred[tid] + sred[128 + tid] + sred[256 + tid] + sred[384 + tid];
            Cf[(size_t)blockIdx.x * M_ + m0 + tid] = s;
        }
        return;
    }

#pragma unroll
    for (int im = 0; im < 4; im++) {
#pragma unroll
        for (int jn = 0; jn < 4; jn++) {
            const int n = n0 + wn + jn * 8 + t4 * 2;
            const float bv0 = bias[n], bv1 = bias[n + 1];
            float ew0 = 0.f, ew1 = 0.f;
            if (EPI == 2) { ew0 = exW[(size_t)n * 257]; ew1 = exW[(size_t)(n + 1) * 257]; }
#pragma unroll
            for (int h = 0; h < 2; h++) {
                const int m = m0 + wm + im * 16 + g + h * 8;
                float v0 = acc[im][jn][h * 2 + 0] + bv0;
                float v1 = acc[im][jn][h * 2 + 1] + bv1;
                if (EPI == 2) {
                    const float ec = exCol[m];
                    v0 += ec * ew0; v1 += ec * ew1;
                }
                if (EPI == 2 || EPI == 3) { v0 = fmaxf(v0, 0.f); v1 = fmaxf(v1, 0.f); }
                const size_t off = (size_t)m * N + n;
                if (EPI != 2)
                    *reinterpret_cast<float2*>(Cf + off) = make_float2(v0, v1);
                if (EPI == 2) {
                    __half2 ph;
                    ph.x = __float2half(v0); ph.y = __float2half(v1);
                    *reinterpret_cast<__half2*>(Chi + off) = ph;
                }
            }
        }
    }
}

// ======================= gated final combine =======================
__global__ void __launch_bounds__(256) gatedfin_k(
    const float* __restrict__ part, const float* __restrict__ gb,
    float* __restrict__ Amat)
{
    int m = blockIdx.x * 256 + threadIdx.x;
    Amat[m] = part[m] + part[M_ + m] + part[2 * M_ + m] + part[3 * M_ + m] + gb[0];
}

// ======================= softmax over T + bag + At =======================
__global__ void __launch_bounds__(256) softbag_kernel(
    const float* __restrict__ Amat, const float* __restrict__ feat,
    float* __restrict__ bag, float* __restrict__ outAt)
{
    __shared__ float p[32];
    int b = blockIdx.x;
    int tid = threadIdx.x;
    if (tid < 32) {
        float v = Amat[b * 32 + tid];
        outAt[b * 32 + tid] = v;
        float mx = v;
#pragma unroll
        for (int o = 16; o; o >>= 1) mx = fmaxf(mx, __shfl_xor_sync(0xffffffffu, mx, o));
        float e = expf(v - mx);
        float s = e;
#pragma unroll
        for (int o = 16; o; o >>= 1) s += __shfl_xor_sync(0xffffffffu, s, o);
        p[tid] = e / s;
    }
    __syncthreads();
    float acc = 0.f;
#pragma unroll 8
    for (int t = 0; t < 32; t++) acc += p[t] * feat[(size_t)(b * 32 + t) * 256 + tid];
    bag[b * 256 + tid] = acc;
}

// ======================= bag classifier =======================
__global__ void __launch_bounds__(256) bagclf_kernel(
    const float* __restrict__ bag,
    const float* __restrict__ w0, const float* __restrict__ b0,
    const float* __restrict__ w1, const float* __restrict__ b1,
    const float* __restrict__ w2, const float* __restrict__ b2,
    const float* __restrict__ w3, const float* __restrict__ b3,
    float* __restrict__ outp)
{
    __shared__ float sb[8 * 256];
    __shared__ float sh[8 * 256];
    int base = blockIdx.x * 8;
    int tid = threadIdx.x;
#pragma unroll
    for (int i = 0; i < 8; i++) sb[tid + i * 256] = bag[(size_t)base * 256 + tid + i * 256];
    __syncthreads();
    {
        float acc[8] = {0, 0, 0, 0, 0, 0, 0, 0};
        const float* w = w0 + (size_t)tid * 256;
        for (int l = 0; l < 256; l++) {
            float wv = w[l];
#pragma unroll
            for (int r = 0; r < 8; r++) acc[r] += wv * sb[r * 256 + l];
        }
        float bb = b0[tid];
#pragma unroll
        for (int r = 0; r < 8; r++) sh[r * 256 + tid] = fmaxf(acc[r] + bb, 0.f);
    }
    __syncthreads();
    if (tid < 128) {
        float acc[8] = {0, 0, 0, 0, 0, 0, 0, 0};
        const float* w = w1 + (size_t)tid * 256;
        for (int l = 0; l < 256; l++) {
            float wv = w[l];
#pragma unroll
            for (int r = 0; r < 8; r++) acc[r] += wv * sh[r * 256 + l];
        }
        float bb = b1[tid];
#pragma unroll
        for (int r = 0; r < 8; r++) sb[r * 128 + tid] = fmaxf(acc[r] + bb, 0.f);
    }
    __syncthreads();
    if (tid < 32) {
        float acc[8] = {0, 0, 0, 0, 0, 0, 0, 0};
        const float* w = w2 + (size_t)tid * 128;
        for (int l = 0; l < 128; l++) {
            float wv = w[l];
#pragma unroll
            for (int r = 0; r < 8; r++) acc[r] += wv * sb[r * 128 + l];
        }
        float bb = b2[tid];
#pragma unroll
        for (int r = 0; r < 8; r++) sh[r * 32 + tid] = fmaxf(acc[r] + bb, 0.f);
    }
    __syncthreads();
    if (tid < 8) {
        float a = 0.f;
        for (int j = 0; j < 32; j++) a += w3[j] * sh[tid * 32 + j];
        float o1 = 1.f / (1.f + expf(-(a + b3[0])));
        outp[(size_t)(base + tid) * 2 + 0] = 0.5f * o1;
    }
}

// ======================= seg tail =======================
__global__ void __launch_bounds__(256) segtail_kernel(
    const float* __restrict__ h1,
    const float* __restrict__ w2, const float* __restrict__ b2,
    const float* __restrict__ w3, const float* __restrict__ b3,
    float* __restrict__ out_seg)
{
    __shared__ float sw2[128 * 32];
    __shared__ float sh1[8 * 128];
    int m0 = blockIdx.x * 8;
    int tid = threadIdx.x;
#pragma unroll
    for (int i = 0; i < 16; i++) {
        int idx = tid + i * 256;
        sw2[(idx & 127) * 32 + (idx >> 7)] = w2[idx];
    }
#pragma unroll
    for (int i = 0; i < 4; i++) {
        int idx = tid + i * 256;
        sh1[idx] = h1[(size_t)m0 * 128 + idx];
    }
    __syncthreads();
    int r = tid >> 5, j = tid & 31;
    float acc = b2[j];
#pragma unroll 8
    for (int l = 0; l < 128; l++) acc += sw2[l * 32 + j] * sh1[r * 128 + l];
    float h2 = fmaxf(acc, 0.f);
    float v = h2 * w3[j];
#pragma unroll
    for (int o = 16; o; o >>= 1) v += __shfl_xor_sync(0xffffffffu, v, o);
    if (j == 0) out_seg[m0 + r] = 1.f / (1.f + expf(-(v + b3[0])));
}

// ======================= per-sample 2-means (unchanged) =======================
__global__ void __launch_bounds__(512, 4) kmeans_assign_k(
    const float* __restrict__ feat,
    float* __restrict__ out_assign, int* __restrict__ out_mask)
{
    __shared__ float sf[32 * 256];
    __shared__ float sc[2 * 256];
    __shared__ int sassign[32];
    int b = blockIdx.x;
    int tid = threadIdx.x;
    int lane = tid & 31, w = tid >> 5;

    {
        const float4* src = reinterpret_cast<const float4*>(feat + (size_t)b * 8192);
        float4* dst = reinterpret_cast<float4*>(sf);
#pragma unroll
        for (int i = 0; i < 4; i++) dst[tid + i * 512] = src[tid + i * 512];
    }
    __syncthreads();
    if (tid < 256) {
        sc[tid] = sf[tid];
        sc[256 + tid] = sf[4096 + tid];
    }
    __syncthreads();

    unsigned prev1 = 0, prev2 = 0, final_mask = 0;
    bool done = false;
    for (int it = 0; it < 100 && !done; it++) {
        float n0 = 0.f, n1 = 0.f, d0a = 0.f, d1a = 0.f, d0b = 0.f, d1b = 0.f;
#pragma unroll
        for (int i = 0; i < 8; i++) {
            int k = lane + i * 32;
            float c0 = sc[k], c1 = sc[256 + k];
            float fa = sf[w * 256 + k], fb = sf[(w + 16) * 256 + k];
            n0 += c0 * c0; n1 += c1 * c1;
            d0a += fa * c0; d1a += fa * c1;
            d0b += fb * c0; d1b += fb * c1;
        }
#pragma unroll
        for (int o = 16; o; o >>= 1) {
            n0  += __shfl_xor_sync(0xffffffffu, n0, o);
            n1  += __shfl_xor_sync(0xffffffffu, n1, o);
            d0a += __shfl_xor_sync(0xffffffffu, d0a, o);
            d1a += __shfl_xor_sync(0xffffffffu, d1a, o);
            d0b += __shfl_xor_sync(0xffffffffu, d0b, o);
            d1b += __shfl_xor_sync(0xffffffffu, d1b, o);
        }
        if (lane == 0) {
            float inv0 = 1.f / (sqrtf(n0) + 1e-8f);
            float inv1 = 1.f / (sqrtf(n1) + 1e-8f);
            sassign[w]      = (d1a * inv1 > d0a * inv0) ? 1 : 0;
            sassign[w + 16] = (d1b * inv1 > d0b * inv0) ? 1 : 0;
        }
        __syncthreads();
        unsigned mask = __ballot_sync(0xffffffffu, sassign[lane] != 0);
        if (it >= 1 && mask == prev1) { final_mask = mask; done = true; }
        else if (it >= 2 && mask == prev2) {
            final_mask = (((99 - it) & 1) == 0) ? mask : prev1;
            done = true;
        } else {
            prev2 = prev1; prev1 = mask; final_mask = mask;
            if (it == 99) done = true;
            else if (tid < 256) {
                int cnt1 = __popc(mask), cnt0 = 32 - cnt1;
                float a0 = 0.f, a1 = 0.f;
#pragma unroll
                for (int t = 0; t < 32; t++) {
                    float fv = sf[t * 256 + tid];
                    if ((mask >> t) & 1) a1 += fv; else a0 += fv;
                }
                if (cnt0 > 0) sc[tid] = a0 / (float)cnt0;
                if (cnt1 > 0) sc[256 + tid] = a1 / (float)cnt1;
            }
        }
        __syncthreads();
    }

    if (tid < 32) {
        out_assign[b * 32 + tid] = (float)((final_mask >> tid) & 1);
        if (tid == 0) out_mask[b] = (int)final_mask;
    }
}

// ======================= output2 join =======================
__global__ void __launch_bounds__(256) out2_k(
    const int* __restrict__ mask_arr, const float* __restrict__ seg,
    float* __restrict__ outp)
{
    int b = blockIdx.x * 8 + (threadIdx.x >> 5);
    int lane = threadIdx.x & 31;
    unsigned mask = (unsigned)mask_arr[b];
    float s = seg[b * 32 + lane];
    int bit = (mask >> lane) & 1;
    float v0 = bit ? 0.f : s;
    float v1 = bit ? s : 0.f;
#pragma unroll
    for (int o = 16; o; o >>= 1) {
        v0 += __shfl_xor_sync(0xffffffffu, v0, o);
        v1 += __shfl_xor_sync(0xffffffffu, v1, o);
    }
    if (lane == 0) {
        int cnt1 = __popc(mask);
        int cnt0 = 32 - cnt1;
        float m0 = (cnt0 > 0) ? v0 / (float)cnt0 : -INFINITY;
        float m1 = (cnt1 > 0) ? v1 / (float)cnt1 : -INFINITY;
        outp[(size_t)b * 2 + 1] = 0.5f * fmaxf(m0, m1);
    }
}

// ======================= launch =======================
extern "C" void kernel_launch(void* const* d_in, const int* in_sizes, int n_in,
                              void* d_out, int out_size)
{
    const float* x      = (const float*)d_in[0];
    const float* tsn_w  = (const float*)d_in[1];
    const float* tsn_b  = (const float*)d_in[2];
    const float* aV_w   = (const float*)d_in[3];
    const float* aV_b   = (const float*)d_in[4];
    const float* aU_w   = (const float*)d_in[5];
    const float* aU_b   = (const float*)d_in[6];
    const float* gate_w = (const float*)d_in[7];
    const float* gate_b = (const float*)d_in[8];
    const float* cb_w0 = (const float*)d_in[9],  *cb_b0 = (const float*)d_in[10];
    const float* cb_w1 = (const float*)d_in[11], *cb_b1 = (const float*)d_in[12];
    const float* cb_w2 = (const float*)d_in[13], *cb_b2 = (const float*)d_in[14];
    const float* cb_w3 = (const float*)d_in[15], *cb_b3 = (const float*)d_in[16];
    const float* cs_w0 = (const float*)d_in[17], *cs_b0 = (const float*)d_in[18];
    const float* cs_w1 = (const float*)d_in[19], *cs_b1 = (const float*)d_in[20];
    const float* cs_w2 = (const float*)d_in[21], *cs_b2 = (const float*)d_in[22];
    const float* cs_w3 = (const float*)d_in[23], *cs_b3 = (const float*)d_in[24];

    float* out = (float*)d_out;
    float* feat    = out + OFF_FEAT;
    float* oAssign = out + OFF_ASSIGN;
    float* oSeg    = out + OFF_SEG;
    float* oOut    = out + OFF_OUT;
    float* oAt     = out + OFF_AT;

    __half *xh, *wt, *bw, *fhi, *h0hi;
    float *part, *Amat, *bag, *h1;
    int* kmask;
    cudaGetSymbolAddress((void**)&xh, g_xh);
    cudaGetSymbolAddress((void**)&wt, g_wt);     cudaGetSymbolAddress((void**)&bw, g_bw);
    cudaGetSymbolAddress((void**)&fhi, g_fhi);   cudaGetSymbolAddress((void**)&h0hi, g_h0hi);
    cudaGetSymbolAddress((void**)&part, g_part);
    cudaGetSymbolAddress((void**)&Amat, g_Amat); cudaGetSymbolAddress((void**)&bag, g_bag);
    cudaGetSymbolAddress((void**)&h1, g_h1);
    cudaGetSymbolAddress((void**)&kmask, g_kmask);

    static cudaStream_t s1 = nullptr, s2 = nullptr;
    static cudaEvent_t evRoot, evX1, evWt, evW, evF, evKm, evA, evSeg;
    if (s1 == nullptr) {
        cudaStreamCreateWithFlags(&s1, cudaStreamNonBlocking);
        cudaStreamCreateWithFlags(&s2, cudaStreamNonBlocking);
        cudaEventCreateWithFlags(&evRoot, cudaEventDisableTiming);
        cudaEventCreateWithFlags(&evX1,   cudaEventDisableTiming);
        cudaEventCreateWithFlags(&evWt,   cudaEventDisableTiming);
        cudaEventCreateWithFlags(&evW,    cudaEventDisableTiming);
        cudaEventCreateWithFlags(&evF,    cudaEventDisableTiming);
        cudaEventCreateWithFlags(&evKm,   cudaEventDisableTiming);
        cudaEventCreateWithFlags(&evA,    cudaEventDisableTiming);
        cudaEventCreateWithFlags(&evSeg,  cudaEventDisableTiming);
    }

    const int SMC  = 3 * 32768 + 2 * 16896;   // 132096: B ring 3x32KB + A ring 2x16.5KB
    const int SMB0 = 2 * 32768;
    cudaFuncSetAttribute(conv_gemm, cudaFuncAttributeMaxDynamicSharedMemorySize, SMC);
    cudaFuncSetAttribute(mm_gemm<5, 2>, cudaFuncAttributeMaxDynamicSharedMemorySize, SMB0);
    cudaFuncSetAttribute(mm_gemm<2, 2>, cudaFuncAttributeMaxDynamicSharedMemorySize, SMB0);
    cudaFuncSetAttribute(mm_gemm<3, 2>, cudaFuncAttributeMaxDynamicSharedMemorySize, SMB0);

    cudaEventRecord(evRoot, 0);
    cudaStreamWaitEvent(s1, evRoot, 0);
    cudaStreamWaitEvent(s2, evRoot, 0);

    // #1: x half0 (main); #2: x half1 (s2); #3: conv weights (s1)
    conv_x_k<<<32768, 256>>>((const float4*)x, (__half2*)xh);
    conv_x_k<<<32768, 256, 0, s2>>>((const float4*)x + 8388608, (__half2*)(xh + 33554432));
    cudaEventRecord(evX1, s2);
    splitw_conv_k<<<(L_ * KCONV) / 256, 256, 0, s1>>>(tsn_w, wt);
    cudaEventRecord(evWt, s1);

    // #4: conv GEMM v4, single launch, 128 CTAs  [PROFILED]
    cudaStreamWaitEvent(0, evWt, 0);
    cudaStreamWaitEvent(0, evX1, 0);
    conv_gemm<<<128, 256, SMC>>>(xh, wt, tsn_b, feat, fhi);
    cudaEventRecord(evF, 0);

    // weight repacks on s1 (overlap conv)
    splitw_pair_k<<<512, 256, 0, s1>>>(aV_w, aU_w, bw);
    splitw_gen_k<<<256, 256, 0, s1>>>(cs_w0, 257, 65536, bw + 131072);
    splitw_gen_k<<<128, 256, 0, s1>>>(cs_w1, 256, 32768, bw + 196608);
    cudaEventRecord(evW, s1);

    // kmeans on s2 after feat
    cudaStreamWaitEvent(s2, evF, 0);
    kmeans_assign_k<<<B_, 512, 0, s2>>>(feat, oAssign, kmask);
    cudaEventRecord(evKm, s2);

    // main chain: fused aVU+gated -> Amat
    cudaStreamWaitEvent(0, evW, 0);
    mm_gemm<5, 2><<<dim3(4, 128), 256, SMB0>>>(fhi, 256, bw, 256,
                                               aV_b, aU_b, gate_w,
                                               part, nullptr, 512, 256);
    gatedfin_k<<<M_ / 256, 256>>>(part, gate_b, Amat);
    cudaEventRecord(evA, 0);

    // seg chain on s1
    cudaStreamWaitEvent(s1, evA, 0);
    mm_gemm<2, 2><<<dim3(2, 128), 256, SMB0, s1>>>(fhi, 256, bw + 131072, 256,
                                                   cs_b0, Amat, cs_w0 + 256,
                                                   nullptr, h0hi, 256, 256);
    mm_gemm<3, 2><<<dim3(1, 128), 256, SMB0, s1>>>(h0hi, 256, bw + 196608, 256,
                                                   cs_b1, nullptr, nullptr,
                                                   h1, nullptr, 128, 256);
    segtail_kernel<<<M_ / 8, 256, 0, s1>>>(h1, cs_w2, cs_b2, cs_w3, cs_b3, oSeg);
    cudaEventRecord(evSeg, s1);

    // bag chain on main stream
    softbag_kernel<<<B_, 256>>>(Amat, feat, bag, oAt);
    bagclf_kernel<<<B_ / 8, 256>>>(bag, cb_w0, cb_b0, cb_w1, cb_b1,
                                   cb_w2, cb_b2, cb_w3, cb_b3, oOut);

    // join
    cudaStreamWaitEvent(0, evSeg, 0);
    cudaStreamWaitEvent(0, evKm, 0);
    out2_k<<<B_ / 8, 256>>>(kmask, oSeg, oOut);
}